// round 10
// baseline (speedup 1.0000x reference)
#include <cuda_runtime.h>
#include <stdint.h>

#define B_  2
#define N_  2048
#define C_  512
#define H_  8
#define HD  64
#define BN_ (B_*N_)
#define BH_ (B_*H_)
#define SCALE 0.04419417382415922f

__device__ float g_xn[(size_t)BN_ * C_];
__device__ float g_q [(size_t)BH_ * N_ * HD];   // [b,h,n,d] scaled+tf32
__device__ float g_k [(size_t)BH_ * N_ * HD];   // [b,h,n,d] tf32
__device__ float g_v [(size_t)BH_ * N_ * HD];   // [b,h,d,n] transposed tf32
__device__ float g_ao[(size_t)BH_ * N_ * HD];   // [b,h,n,d] tf32
__device__ float g_wt[4][(size_t)C_ * C_];      // transposed [n][k] tf32

__device__ __forceinline__ uint32_t f2tf(float f) {
    uint32_t u; asm("cvt.rna.tf32.f32 %0, %1;" : "=r"(u) : "f"(f)); return u;
}
__device__ __forceinline__ float f2tff(float f) { return __uint_as_float(f2tf(f)); }

__device__ __forceinline__ void mma_tf32(float c[4],
    uint32_t a0, uint32_t a1, uint32_t a2, uint32_t a3, uint32_t b0, uint32_t b1)
{
    asm volatile(
        "mma.sync.aligned.m16n8k8.row.col.f32.tf32.tf32.f32 "
        "{%0,%1,%2,%3}, {%4,%5,%6,%7}, {%8,%9}, {%0,%1,%2,%3};"
        : "+f"(c[0]), "+f"(c[1]), "+f"(c[2]), "+f"(c[3])
        : "r"(a0), "r"(a1), "r"(a2), "r"(a3), "r"(b0), "r"(b1));
}
__device__ __forceinline__ void ldsm4(uint32_t& r0, uint32_t& r1, uint32_t& r2,
                                      uint32_t& r3, uint32_t a)
{
    asm volatile("ldmatrix.sync.aligned.m8n8.x4.shared.b16 {%0,%1,%2,%3}, [%4];"
        : "=r"(r0), "=r"(r1), "=r"(r2), "=r"(r3) : "r"(a));
}
__device__ __forceinline__ void cp16(uint32_t dst, const void* src) {
    asm volatile("cp.async.cg.shared.global [%0], [%1], 16;" :: "r"(dst), "l"(src));
}
#define CPCOMMIT() asm volatile("cp.async.commit_group;")
#define CPWAIT0()  asm volatile("cp.async.wait_group 0;")

// ---------------- weight prep: transpose + tf32 round -------------------------
__global__ __launch_bounds__(256) void prep_w(
    const float* __restrict__ wq, const float* __restrict__ wk,
    const float* __restrict__ wv, const float* __restrict__ wo)
{
    __shared__ float tile[32][33];
    int m = blockIdx.z;
    const float* s = (m == 0) ? wq : (m == 1) ? wk : (m == 2) ? wv : wo;
    int x0 = blockIdx.x * 32, y0 = blockIdx.y * 32;
    int tx = threadIdx.x & 31, ty = threadIdx.x >> 5;
    #pragma unroll
    for (int i = 0; i < 4; i++)
        tile[ty + 8 * i][tx] = s[(size_t)(y0 + ty + 8 * i) * C_ + x0 + tx];
    __syncthreads();
    #pragma unroll
    for (int i = 0; i < 4; i++)
        g_wt[m][(size_t)(x0 + ty + 8 * i) * C_ + y0 + tx] = f2tff(tile[tx][ty + 8 * i]);
}

// ---------------- LayerNorm (tf32-rounded output) ----------------------------
__global__ __launch_bounds__(128) void ln_kernel(
    const float* __restrict__ x, const float* __restrict__ g,
    const float* __restrict__ bta, float* __restrict__ xn)
{
    int row = blockIdx.x, tid = threadIdx.x;
    float4 v = reinterpret_cast<const float4*>(x + (size_t)row * C_)[tid];
    float s = v.x + v.y + v.z + v.w;
    float ss = v.x*v.x + v.y*v.y + v.z*v.z + v.w*v.w;
    #pragma unroll
    for (int o = 16; o; o >>= 1) {
        s  += __shfl_xor_sync(~0u, s,  o);
        ss += __shfl_xor_sync(~0u, ss, o);
    }
    __shared__ float sh[8];
    int w = tid >> 5, l = tid & 31;
    if (l == 0) { sh[w] = s; sh[4 + w] = ss; }
    __syncthreads();
    float st = sh[0]+sh[1]+sh[2]+sh[3], sst = sh[4]+sh[5]+sh[6]+sh[7];
    float mean = st * (1.0f / C_);
    float var  = sst * (1.0f / C_) - mean * mean;
    float r = rsqrtf(var + 1e-5f);
    float4 gg = reinterpret_cast<const float4*>(g)[tid];
    float4 bb = reinterpret_cast<const float4*>(bta)[tid];
    float4 o;
    o.x = f2tff((v.x - mean) * r * gg.x + bb.x);
    o.y = f2tff((v.y - mean) * r * gg.y + bb.y);
    o.z = f2tff((v.z - mean) * r * gg.z + bb.z);
    o.w = f2tff((v.w - mean) * r * gg.w + bb.w);
    reinterpret_cast<float4*>(xn + (size_t)row * C_)[tid] = o;
}

// ============================================================================
// GEMM (round-5 verified): 64x64 CTA tile, BK=32, 128 thr, 4 warps (2Mx2N).
// ============================================================================
__device__ __forceinline__ void gemm_frag_compute(
    const uint32_t* sA, const uint32_t* sB, int buf,
    int wM, int wN, int g, int c, float acc[2][4][4])
{
    #pragma unroll
    for (int ks = 0; ks < 4; ks++) {
        uint32_t a[2][4], b[4][2];
        #pragma unroll
        for (int mf = 0; mf < 2; mf++) {
            const uint32_t* ap = sA + buf * 2304 + (wM * 32 + mf * 16 + g) * 36 + ks * 8;
            a[mf][0] = ap[c];
            a[mf][1] = ap[8 * 36 + c];
            a[mf][2] = ap[c + 4];
            a[mf][3] = ap[8 * 36 + c + 4];
        }
        #pragma unroll
        for (int nf = 0; nf < 4; nf++) {
            const uint32_t* bp = sB + buf * 2304 + (wN * 32 + nf * 8 + g) * 36 + ks * 8;
            b[nf][0] = bp[c];
            b[nf][1] = bp[c + 4];
        }
        #pragma unroll
        for (int mf = 0; mf < 2; mf++)
            #pragma unroll
            for (int nf = 0; nf < 4; nf++)
                mma_tf32(acc[mf][nf], a[mf][0], a[mf][1], a[mf][2], a[mf][3],
                         b[nf][0], b[nf][1]);
    }
}

__global__ __launch_bounds__(128) void qkv_gemm(
    const float* __restrict__ A,
    const float* __restrict__ bq, const float* __restrict__ bk, const float* __restrict__ bv,
    float* __restrict__ Q, float* __restrict__ K, float* __restrict__ V)
{
    __shared__ __align__(16) uint32_t sA[2 * 2304];
    __shared__ __align__(16) uint32_t sB[2 * 2304];
    uint32_t aB = (uint32_t)__cvta_generic_to_shared(sA);
    uint32_t bB = (uint32_t)__cvta_generic_to_shared(sB);

    int z = blockIdx.z;
    const float* Wt = &g_wt[z][0];
    const float* bias = (z == 0) ? bq : (z == 1) ? bk : bv;

    int tid = threadIdx.x, lane = tid & 31, wid = tid >> 5;
    int wM = wid >> 1, wN = wid & 1, g = lane >> 2, c = lane & 3;
    int rowbase = blockIdx.y * 64, colbase = blockIdx.x * 64;

    #pragma unroll
    for (int p = 0; p < 4; p++) {
        int idx = tid + p * 128;
        int r = idx >> 3, k4 = idx & 7;
        uint32_t off = (uint32_t)(r * 36 + k4 * 4) * 4;
        cp16(aB + off, A  + (size_t)(rowbase + r) * C_ + k4 * 4);
        cp16(bB + off, Wt + (size_t)(colbase + r) * C_ + k4 * 4);
    }
    CPCOMMIT();

    float acc[2][4][4] = {};
    for (int t = 0; t < 16; t++) {
        int buf = t & 1;
        CPWAIT0();
        __syncthreads();
        if (t < 15) {
            int k0 = (t + 1) * 32;
            uint32_t bo = (uint32_t)((buf ^ 1) * 2304) * 4;
            #pragma unroll
            for (int p = 0; p < 4; p++) {
                int idx = tid + p * 128;
                int r = idx >> 3, k4 = idx & 7;
                uint32_t off = bo + (uint32_t)(r * 36 + k4 * 4) * 4;
                cp16(aB + off, A  + (size_t)(rowbase + r) * C_ + k0 + k4 * 4);
                cp16(bB + off, Wt + (size_t)(colbase + r) * C_ + k0 + k4 * 4);
            }
            CPCOMMIT();
        }
        gemm_frag_compute(sA, sB, buf, wM, wN, g, c, acc);
    }

    int h = blockIdx.x;
    int bb = rowbase >> 11, nbase = rowbase & (N_ - 1);
    if (z != 2) {
        float* out = z ? K : Q;
        float sc = z ? 1.0f : SCALE;
        #pragma unroll
        for (int mf = 0; mf < 2; mf++) {
            int rl = wM * 32 + mf * 16 + g;
            #pragma unroll
            for (int nf = 0; nf < 4; nf++) {
                int d = wN * 32 + nf * 8 + 2 * c;
                float b0 = bias[colbase + d], b1 = bias[colbase + d + 1];
                float* o0 = out + (((size_t)bb * H_ + h) * N_ + nbase + rl) * HD + d;
                float* o1 = out + (((size_t)bb * H_ + h) * N_ + nbase + rl + 8) * HD + d;
                *reinterpret_cast<float2*>(o0) =
                    make_float2(f2tff((acc[mf][nf][0] + b0) * sc), f2tff((acc[mf][nf][1] + b1) * sc));
                *reinterpret_cast<float2*>(o1) =
                    make_float2(f2tff((acc[mf][nf][2] + b0) * sc), f2tff((acc[mf][nf][3] + b1) * sc));
            }
        }
    } else {
        __syncthreads();
        float* tb = (float*)sA;   // [64][65]
        #pragma unroll
        for (int mf = 0; mf < 2; mf++) {
            int rl = wM * 32 + mf * 16 + g;
            #pragma unroll
            for (int nf = 0; nf < 4; nf++) {
                int d = wN * 32 + nf * 8 + 2 * c;
                float b0 = bias[colbase + d], b1 = bias[colbase + d + 1];
                tb[d * 65 + rl]           = f2tff(acc[mf][nf][0] + b0);
                tb[(d + 1) * 65 + rl]     = f2tff(acc[mf][nf][1] + b1);
                tb[d * 65 + rl + 8]       = f2tff(acc[mf][nf][2] + b0);
                tb[(d + 1) * 65 + rl + 8] = f2tff(acc[mf][nf][3] + b1);
            }
        }
        __syncthreads();
        #pragma unroll
        for (int p = 0; p < 8; p++) {
            int idx = tid + p * 128;
            int d = idx >> 4, n4 = idx & 15;
            float4 val = make_float4(tb[d * 65 + n4 * 4],     tb[d * 65 + n4 * 4 + 1],
                                     tb[d * 65 + n4 * 4 + 2], tb[d * 65 + n4 * 4 + 3]);
            *reinterpret_cast<float4*>(
                V + (((size_t)bb * H_ + h) * HD + d) * N_ + nbase + n4 * 4) = val;
        }
    }
}

// ============================================================================
// Flash attention: 128 q/CTA, 4 warps x 32 q-rows (2 m-frags), 64-key tiles.
// QK/softmax/P-store run per m-frag sequentially -> live sacc halved (32 regs)
// to stay under the spill threshold. PV joint (B-frags shared across mf).
// smem words: Ks 2*4352, Vs 2*4352, Ps 4*2176=8704, ms 128  -> 26240 (102.5 KB)
// ============================================================================
#define AKS(buf) ((buf) * 4352)
#define AVS(buf) (8704 + (buf) * 4352)
#define APS      17408
#define AMS      26112
#define ATTN_SMB (26240 * 4)

__global__ __launch_bounds__(128, 2) void attn_t(
    const float* __restrict__ Q, const float* __restrict__ K,
    const float* __restrict__ Vt, const int* __restrict__ mask,
    float* __restrict__ O)
{
    extern __shared__ uint32_t sm[];
    float* ms = (float*)(sm + AMS);
    uint32_t sb = (uint32_t)__cvta_generic_to_shared(sm);

    int bh = blockIdx.y, b = bh >> 3;
    int qbase = blockIdx.x * 128;
    int tid = threadIdx.x, wid = tid >> 5, lane = tid & 31;
    int g = lane >> 2, c = lane & 3;
    int r0 = qbase + wid * 32 + g;
    const size_t kvb = (size_t)bh * N_ * HD;

    int sel = lane >> 3, l8 = lane & 7;
    uint32_t ofB = (uint32_t)((((sel >> 1) * 8 + l8) * 68 + (sel & 1) * 4) * 4);
    uint32_t ofA = (uint32_t)((((sel & 1) * 8 + l8) * 68 + (sel >> 1) * 4) * 4);
    uint32_t pbase = sb + (uint32_t)((APS + wid * 2176) * 4) + ofA;

    // Q fragments: 2 m-frags (rows r0.., r0+16..)
    uint32_t qf[2][8][4];
    #pragma unroll
    for (int mf = 0; mf < 2; mf++) {
        const uint32_t* Qp = reinterpret_cast<const uint32_t*>(
            Q + ((size_t)bh * N_ + r0 + 16 * mf) * HD);
        #pragma unroll
        for (int ks = 0; ks < 8; ks++) {
            qf[mf][ks][0] = Qp[ks * 8 + c];
            qf[mf][ks][1] = Qp[8 * HD + ks * 8 + c];
            qf[mf][ks][2] = Qp[ks * 8 + c + 4];
            qf[mf][ks][3] = Qp[8 * HD + ks * 8 + c + 4];
        }
    }

    #pragma unroll
    for (int p = 0; p < 8; p++) {
        int idx = tid + p * 128;
        int key = idx >> 4, d4 = idx & 15;
        cp16(sb + (uint32_t)(AKS(0) + key * 68 + d4 * 4) * 4,
             K + kvb + (size_t)key * HD + d4 * 4);
    }
    #pragma unroll
    for (int p = 0; p < 8; p++) {
        int idx = tid + p * 128;
        int d = idx >> 4, k4 = idx & 15;
        cp16(sb + (uint32_t)(AVS(0) + d * 68 + k4 * 4) * 4,
             Vt + kvb + (size_t)d * N_ + k4 * 4);
    }
    CPCOMMIT();
    if (tid < 64) ms[tid] = mask[b * N_ + tid] ? 0.0f : -10000.0f;

    float of[2][8][4] = {};
    float mx[4] = {-1e30f, -1e30f, -1e30f, -1e30f};
    float lsum[4] = {};

    for (int t = 0; t < 32; t++) {
        int buf = t & 1;
        CPWAIT0();
        __syncthreads();
        int mreg = 0;
        if (t < 31) {
            int kn = (t + 1) * 64;
            #pragma unroll
            for (int p = 0; p < 8; p++) {
                int idx = tid + p * 128;
                int key = idx >> 4, d4 = idx & 15;
                cp16(sb + (uint32_t)(AKS(buf ^ 1) + key * 68 + d4 * 4) * 4,
                     K + kvb + (size_t)(kn + key) * HD + d4 * 4);
            }
            #pragma unroll
            for (int p = 0; p < 8; p++) {
                int idx = tid + p * 128;
                int d = idx >> 4, k4 = idx & 15;
                cp16(sb + (uint32_t)(AVS(buf ^ 1) + d * 68 + k4 * 4) * 4,
                     Vt + kvb + (size_t)d * N_ + kn + k4 * 4);
            }
            CPCOMMIT();
            if (tid < 64) mreg = mask[b * N_ + kn + tid];
        }

        uint32_t kb = sb + (uint32_t)(AKS(buf) * 4) + ofB;
        const float* msp = ms + buf * 64;
        uint32_t* Ps = sm + APS + wid * 2176;

        // per m-frag: S = QK^T, mask, online softmax, exp, P-store
        #pragma unroll
        for (int mf = 0; mf < 2; mf++) {
            float sacc[8][4] = {};
            #pragma unroll
            for (int ks = 0; ks < 8; ks++) {
                #pragma unroll
                for (int p = 0; p < 4; p++) {
                    uint32_t b0, b1, b2, b3;
                    ldsm4(b0, b1, b2, b3, kb + (uint32_t)((p * 1088 + ks * 8) * 4));
                    mma_tf32(sacc[2*p],   qf[mf][ks][0], qf[mf][ks][1],
                             qf[mf][ks][2], qf[mf][ks][3], b0, b1);
                    mma_tf32(sacc[2*p+1], qf[mf][ks][0], qf[mf][ks][1],
                             qf[mf][ks][2], qf[mf][ks][3], b2, b3);
                }
            }

            float t0 = -1e30f, t1 = -1e30f;
            #pragma unroll
            for (int nf = 0; nf < 8; nf++) {
                float ma = msp[nf * 8 + 2 * c], mb = msp[nf * 8 + 2 * c + 1];
                sacc[nf][0] += ma; sacc[nf][1] += mb;
                sacc[nf][2] += ma; sacc[nf][3] += mb;
                t0 = fmaxf(t0, fmaxf(sacc[nf][0], sacc[nf][1]));
                t1 = fmaxf(t1, fmaxf(sacc[nf][2], sacc[nf][3]));
            }
            t0 = fmaxf(t0, __shfl_xor_sync(~0u, t0, 1));
            t0 = fmaxf(t0, __shfl_xor_sync(~0u, t0, 2));
            t1 = fmaxf(t1, __shfl_xor_sync(~0u, t1, 1));
            t1 = fmaxf(t1, __shfl_xor_sync(~0u, t1, 2));
            float mn0 = fmaxf(mx[mf*2],   t0);
            float mn1 = fmaxf(mx[mf*2+1], t1);
            if (mn0 > mx[mf*2] || mn1 > mx[mf*2+1]) {
                float co0 = __expf(mx[mf*2] - mn0), co1 = __expf(mx[mf*2+1] - mn1);
                lsum[mf*2] *= co0; lsum[mf*2+1] *= co1;
                #pragma unroll
                for (int nf = 0; nf < 8; nf++) {
                    of[mf][nf][0] *= co0; of[mf][nf][1] *= co0;
                    of[mf][nf][2] *= co1; of[mf][nf][3] *= co1;
                }
                mx[mf*2] = mn0; mx[mf*2+1] = mn1;
            }

            int rl = 16 * mf + g;
            #pragma unroll
            for (int nf = 0; nf < 8; nf++) {
                float p0 = __expf(sacc[nf][0] - mx[mf*2]);
                float p1 = __expf(sacc[nf][1] - mx[mf*2]);
                float p2 = __expf(sacc[nf][2] - mx[mf*2+1]);
                float p3 = __expf(sacc[nf][3] - mx[mf*2+1]);
                lsum[mf*2]   += p0 + p1;
                lsum[mf*2+1] += p2 + p3;
                *reinterpret_cast<uint2*>(&Ps[rl * 68 + nf * 8 + 2 * c]) =
                    make_uint2(f2tf(p0), f2tf(p1));
                *reinterpret_cast<uint2*>(&Ps[(rl + 8) * 68 + nf * 8 + 2 * c]) =
                    make_uint2(f2tf(p2), f2tf(p3));
            }
        }
        __syncwarp();

        // O += P V : A-frags via ldsm (2 per ks), B-frags shared across mf
        uint32_t vb = sb + (uint32_t)(AVS(buf) * 4) + ofB;
        #pragma unroll
        for (int ks = 0; ks < 8; ks++) {
            uint32_t a[2][4];
            ldsm4(a[0][0], a[0][1], a[0][2], a[0][3], pbase + (uint32_t)(ks * 32));
            ldsm4(a[1][0], a[1][1], a[1][2], a[1][3],
                  pbase + (uint32_t)(16 * 68 * 4 + ks * 32));
            #pragma unroll
            for (int p = 0; p < 4; p++) {
                uint32_t b0, b1, b2, b3;
                ldsm4(b0, b1, b2, b3, vb + (uint32_t)((p * 1088 + ks * 8) * 4));
                #pragma unroll
                for (int mf = 0; mf < 2; mf++) {
                    mma_tf32(of[mf][2*p],   a[mf][0], a[mf][1], a[mf][2], a[mf][3], b0, b1);
                    mma_tf32(of[mf][2*p+1], a[mf][0], a[mf][1], a[mf][2], a[mf][3], b2, b3);
                }
            }
        }
        if (t < 31 && tid < 64)
            ms[(buf ^ 1) * 64 + tid] = mreg ? 0.0f : -10000.0f;
    }

    #pragma unroll
    for (int i = 0; i < 4; i++) {
        lsum[i] += __shfl_xor_sync(~0u, lsum[i], 1);
        lsum[i] += __shfl_xor_sync(~0u, lsum[i], 2);
    }
    #pragma unroll
    for (int mf = 0; mf < 2; mf++) {
        float inv0 = 1.0f / lsum[mf*2], inv1 = 1.0f / lsum[mf*2+1];
        float* Op = O + ((size_t)bh * N_ + r0 + 16 * mf) * HD;
        #pragma unroll
        for (int nf = 0; nf < 8; nf++) {
            int d = nf * 8 + 2 * c;
            *reinterpret_cast<float2*>(Op + d) =
                make_float2(f2tff(of[mf][nf][0] * inv0), f2tff(of[mf][nf][1] * inv0));
            *reinterpret_cast<float2*>(Op + 8 * HD + d) =
                make_float2(f2tff(of[mf][nf][2] * inv1), f2tff(of[mf][nf][3] * inv1));
        }
    }
}

// ---------------- Output projection (round-5 verified) ------------------------
__global__ __launch_bounds__(128) void out_gemm(
    const float* __restrict__ AO, const float* __restrict__ bias, float* __restrict__ out)
{
    __shared__ __align__(16) uint32_t sA[2 * 2304];
    __shared__ __align__(16) uint32_t sB[2 * 2304];
    uint32_t aB = (uint32_t)__cvta_generic_to_shared(sA);
    uint32_t bB = (uint32_t)__cvta_generic_to_shared(sB);
    const float* Wt = &g_wt[3][0];

    int tid = threadIdx.x, lane = tid & 31, wid = tid >> 5;
    int wM = wid >> 1, wN = wid & 1, g = lane >> 2, c = lane & 3;
    int rowbase = blockIdx.y * 64, colbase = blockIdx.x * 64;
    int bb = rowbase >> 11, nbase = rowbase & (N_ - 1);

    #pragma unroll
    for (int p = 0; p < 4; p++) {
        int idx = tid + p * 128;
        int r = idx >> 3, k4 = idx & 7;
        int k = k4 * 4, h = k >> 6, d = k & 63;
        uint32_t off = (uint32_t)(r * 36 + k4 * 4) * 4;
        cp16(aB + off, AO + (((size_t)bb * H_ + h) * N_ + nbase + r) * HD + d);
        cp16(bB + off, Wt + (size_t)(colbase + r) * C_ + k4 * 4);
    }
    CPCOMMIT();

    float acc[2][4][4] = {};
    for (int t = 0; t < 16; t++) {
        int buf = t & 1;
        CPWAIT0();
        __syncthreads();
        if (t < 15) {
            int k0 = (t + 1) * 32;
            uint32_t bo = (uint32_t)((buf ^ 1) * 2304) * 4;
            #pragma unroll
            for (int p = 0; p < 4; p++) {
                int idx = tid + p * 128;
                int r = idx >> 3, k4 = idx & 7;
                int k = k0 + k4 * 4, h = k >> 6, d = k & 63;
                uint32_t off = bo + (uint32_t)(r * 36 + k4 * 4) * 4;
                cp16(aB + off, AO + (((size_t)bb * H_ + h) * N_ + nbase + r) * HD + d);
                cp16(bB + off, Wt + (size_t)(colbase + r) * C_ + k0 + k4 * 4);
            }
            CPCOMMIT();
        }
        gemm_frag_compute(sA, sB, buf, wM, wN, g, c, acc);
    }

    #pragma unroll
    for (int mf = 0; mf < 2; mf++) {
        int r = rowbase + wM * 32 + mf * 16 + g;
        #pragma unroll
        for (int nf = 0; nf < 4; nf++) {
            int cc = colbase + wN * 32 + nf * 8 + 2 * c;
            float b0 = bias[cc], b1 = bias[cc + 1];
            *reinterpret_cast<float2*>(out + (size_t)r * C_ + cc) =
                make_float2(acc[mf][nf][0] + b0, acc[mf][nf][1] + b1);
            *reinterpret_cast<float2*>(out + (size_t)(r + 8) * C_ + cc) =
                make_float2(acc[mf][nf][2] + b0, acc[mf][nf][3] + b1);
        }
    }
}

// ---------------- launch -------------------------------------------------------
extern "C" void kernel_launch(void* const* d_in, const int* in_sizes, int n_in,
                              void* d_out, int out_size)
{
    const float* x    = (const float*)d_in[0];
    const int*   mask = (const int*)  d_in[1];
    const float* ln_g = (const float*)d_in[2];
    const float* ln_b = (const float*)d_in[3];
    const float* wq   = (const float*)d_in[4];
    const float* bq   = (const float*)d_in[5];
    const float* wk   = (const float*)d_in[6];
    const float* bk   = (const float*)d_in[7];
    const float* wv   = (const float*)d_in[8];
    const float* bv   = (const float*)d_in[9];
    const float* wo   = (const float*)d_in[10];
    const float* bo   = (const float*)d_in[11];
    float* out = (float*)d_out;

    float *xn, *q, *k, *v, *ao;
    cudaGetSymbolAddress((void**)&xn, g_xn);
    cudaGetSymbolAddress((void**)&q,  g_q);
    cudaGetSymbolAddress((void**)&k,  g_k);
    cudaGetSymbolAddress((void**)&v,  g_v);
    cudaGetSymbolAddress((void**)&ao, g_ao);

    cudaFuncSetAttribute(attn_t, cudaFuncAttributeMaxDynamicSharedMemorySize, ATTN_SMB);

    prep_w<<<dim3(16, 16, 4), 256>>>(wq, wk, wv, wo);
    ln_kernel<<<BN_, 128>>>(x, ln_g, ln_b, xn);
    qkv_gemm<<<dim3(C_ / 64, BN_ / 64, 3), 128>>>(xn, bq, bk, bv, q, k, v);
    attn_t<<<dim3(N_ / 128, BH_), 128, ATTN_SMB>>>(q, k, v, mask, ao);
    out_gemm<<<dim3(C_ / 64, BN_ / 64), 128>>>(ao, bo, out);
}

// round 11
// speedup vs baseline: 1.0819x; 1.0819x over previous
#include <cuda_runtime.h>
#include <stdint.h>

#define B_  2
#define N_  2048
#define C_  512
#define H_  8
#define HD  64
#define BN_ (B_*N_)
#define BH_ (B_*H_)
#define SCALE 0.04419417382415922f

__device__ float g_xn[(size_t)BN_ * C_];
__device__ float g_q [(size_t)BH_ * N_ * HD];   // [b,h,n,d] scaled+tf32
__device__ float g_k [(size_t)BH_ * N_ * HD];   // [b,h,n,d] tf32
__device__ float g_v [(size_t)BH_ * N_ * HD];   // [b,h,d,n] transposed tf32
__device__ float g_ao[(size_t)BH_ * N_ * HD];   // [b,h,n,d] tf32
__device__ float g_wt[4][(size_t)C_ * C_];      // transposed [n][k] tf32

__device__ __forceinline__ uint32_t f2tf(float f) {
    uint32_t u; asm("cvt.rna.tf32.f32 %0, %1;" : "=r"(u) : "f"(f)); return u;
}
__device__ __forceinline__ float f2tff(float f) { return __uint_as_float(f2tf(f)); }

__device__ __forceinline__ void mma_tf32(float c[4],
    uint32_t a0, uint32_t a1, uint32_t a2, uint32_t a3, uint32_t b0, uint32_t b1)
{
    asm volatile(
        "mma.sync.aligned.m16n8k8.row.col.f32.tf32.tf32.f32 "
        "{%0,%1,%2,%3}, {%4,%5,%6,%7}, {%8,%9}, {%0,%1,%2,%3};"
        : "+f"(c[0]), "+f"(c[1]), "+f"(c[2]), "+f"(c[3])
        : "r"(a0), "r"(a1), "r"(a2), "r"(a3), "r"(b0), "r"(b1));
}
__device__ __forceinline__ void ldsm4(uint32_t& r0, uint32_t& r1, uint32_t& r2,
                                      uint32_t& r3, uint32_t a)
{
    asm volatile("ldmatrix.sync.aligned.m8n8.x4.shared.b16 {%0,%1,%2,%3}, [%4];"
        : "=r"(r0), "=r"(r1), "=r"(r2), "=r"(r3) : "r"(a));
}
__device__ __forceinline__ void cp16(uint32_t dst, const void* src) {
    asm volatile("cp.async.cg.shared.global [%0], [%1], 16;" :: "r"(dst), "l"(src));
}
#define CPCOMMIT() asm volatile("cp.async.commit_group;")
#define CPWAIT0()  asm volatile("cp.async.wait_group 0;")

// ---------------- weight prep: transpose + tf32 round -------------------------
__global__ __launch_bounds__(256) void prep_w(
    const float* __restrict__ wq, const float* __restrict__ wk,
    const float* __restrict__ wv, const float* __restrict__ wo)
{
    __shared__ float tile[32][33];
    int m = blockIdx.z;
    const float* s = (m == 0) ? wq : (m == 1) ? wk : (m == 2) ? wv : wo;
    int x0 = blockIdx.x * 32, y0 = blockIdx.y * 32;
    int tx = threadIdx.x & 31, ty = threadIdx.x >> 5;
    #pragma unroll
    for (int i = 0; i < 4; i++)
        tile[ty + 8 * i][tx] = s[(size_t)(y0 + ty + 8 * i) * C_ + x0 + tx];
    __syncthreads();
    #pragma unroll
    for (int i = 0; i < 4; i++)
        g_wt[m][(size_t)(x0 + ty + 8 * i) * C_ + y0 + tx] = f2tff(tile[tx][ty + 8 * i]);
}

// ---------------- LayerNorm (tf32-rounded output) ----------------------------
__global__ __launch_bounds__(128) void ln_kernel(
    const float* __restrict__ x, const float* __restrict__ g,
    const float* __restrict__ bta, float* __restrict__ xn)
{
    int row = blockIdx.x, tid = threadIdx.x;
    float4 v = reinterpret_cast<const float4*>(x + (size_t)row * C_)[tid];
    float s = v.x + v.y + v.z + v.w;
    float ss = v.x*v.x + v.y*v.y + v.z*v.z + v.w*v.w;
    #pragma unroll
    for (int o = 16; o; o >>= 1) {
        s  += __shfl_xor_sync(~0u, s,  o);
        ss += __shfl_xor_sync(~0u, ss, o);
    }
    __shared__ float sh[8];
    int w = tid >> 5, l = tid & 31;
    if (l == 0) { sh[w] = s; sh[4 + w] = ss; }
    __syncthreads();
    float st = sh[0]+sh[1]+sh[2]+sh[3], sst = sh[4]+sh[5]+sh[6]+sh[7];
    float mean = st * (1.0f / C_);
    float var  = sst * (1.0f / C_) - mean * mean;
    float r = rsqrtf(var + 1e-5f);
    float4 gg = reinterpret_cast<const float4*>(g)[tid];
    float4 bb = reinterpret_cast<const float4*>(bta)[tid];
    float4 o;
    o.x = f2tff((v.x - mean) * r * gg.x + bb.x);
    o.y = f2tff((v.y - mean) * r * gg.y + bb.y);
    o.z = f2tff((v.z - mean) * r * gg.z + bb.z);
    o.w = f2tff((v.w - mean) * r * gg.w + bb.w);
    reinterpret_cast<float4*>(xn + (size_t)row * C_)[tid] = o;
}

// ============================================================================
// GEMM: 64x64 CTA tile, BK=32, 128 thr, 4 warps (2Mx2N), stride-36 smem,
// fragment fetch via ldmatrix.x4 (A: 2/ks, B: 2/ks vs 16 LDS.32/ks).
// ============================================================================
__device__ __forceinline__ void gemm_frag_compute(
    uint32_t aBase, uint32_t bBase, int buf, int wM, int wN,
    uint32_t ofAg, uint32_t ofBg, float acc[2][4][4])
{
    #pragma unroll
    for (int ks = 0; ks < 4; ks++) {
        uint32_t a[2][4], b[4][2];
        #pragma unroll
        for (int mf = 0; mf < 2; mf++)
            ldsm4(a[mf][0], a[mf][1], a[mf][2], a[mf][3],
                  aBase + (uint32_t)((buf * 2304 + (wM * 32 + mf * 16) * 36 + ks * 8) * 4) + ofAg);
        #pragma unroll
        for (int p = 0; p < 2; p++) {
            uint32_t b0, b1, b2, b3;
            ldsm4(b0, b1, b2, b3,
                  bBase + (uint32_t)((buf * 2304 + (wN * 32 + p * 16) * 36 + ks * 8) * 4) + ofBg);
            b[2*p][0] = b0; b[2*p][1] = b1;
            b[2*p+1][0] = b2; b[2*p+1][1] = b3;
        }
        #pragma unroll
        for (int mf = 0; mf < 2; mf++)
            #pragma unroll
            for (int nf = 0; nf < 4; nf++)
                mma_tf32(acc[mf][nf], a[mf][0], a[mf][1], a[mf][2], a[mf][3],
                         b[nf][0], b[nf][1]);
    }
}

__global__ __launch_bounds__(128) void qkv_gemm(
    const float* __restrict__ A,
    const float* __restrict__ bq, const float* __restrict__ bk, const float* __restrict__ bv,
    float* __restrict__ Q, float* __restrict__ K, float* __restrict__ V)
{
    __shared__ __align__(16) uint32_t sA[2 * 2304];
    __shared__ __align__(16) uint32_t sB[2 * 2304];
    uint32_t aB = (uint32_t)__cvta_generic_to_shared(sA);
    uint32_t bB = (uint32_t)__cvta_generic_to_shared(sB);

    int z = blockIdx.z;
    const float* Wt = &g_wt[z][0];
    const float* bias = (z == 0) ? bq : (z == 1) ? bk : bv;

    int tid = threadIdx.x, lane = tid & 31, wid = tid >> 5;
    int wM = wid >> 1, wN = wid & 1, g = lane >> 2, c = lane & 3;
    int rowbase = blockIdx.y * 64, colbase = blockIdx.x * 64;

    int sel = lane >> 3, l8 = lane & 7;
    uint32_t ofAg = (uint32_t)((((sel & 1) * 8 + l8) * 36 + (sel >> 1) * 4) * 4);
    uint32_t ofBg = (uint32_t)((((sel >> 1) * 8 + l8) * 36 + (sel & 1) * 4) * 4);

    #pragma unroll
    for (int p = 0; p < 4; p++) {
        int idx = tid + p * 128;
        int r = idx >> 3, k4 = idx & 7;
        uint32_t off = (uint32_t)(r * 36 + k4 * 4) * 4;
        cp16(aB + off, A  + (size_t)(rowbase + r) * C_ + k4 * 4);
        cp16(bB + off, Wt + (size_t)(colbase + r) * C_ + k4 * 4);
    }
    CPCOMMIT();

    float acc[2][4][4] = {};
    for (int t = 0; t < 16; t++) {
        int buf = t & 1;
        CPWAIT0();
        __syncthreads();
        if (t < 15) {
            int k0 = (t + 1) * 32;
            uint32_t bo = (uint32_t)((buf ^ 1) * 2304) * 4;
            #pragma unroll
            for (int p = 0; p < 4; p++) {
                int idx = tid + p * 128;
                int r = idx >> 3, k4 = idx & 7;
                uint32_t off = bo + (uint32_t)(r * 36 + k4 * 4) * 4;
                cp16(aB + off, A  + (size_t)(rowbase + r) * C_ + k0 + k4 * 4);
                cp16(bB + off, Wt + (size_t)(colbase + r) * C_ + k0 + k4 * 4);
            }
            CPCOMMIT();
        }
        gemm_frag_compute(aB, bB, buf, wM, wN, ofAg, ofBg, acc);
    }

    int h = blockIdx.x;
    int bb = rowbase >> 11, nbase = rowbase & (N_ - 1);
    if (z != 2) {
        float* out = z ? K : Q;
        float sc = z ? 1.0f : SCALE;
        #pragma unroll
        for (int mf = 0; mf < 2; mf++) {
            int rl = wM * 32 + mf * 16 + g;
            #pragma unroll
            for (int nf = 0; nf < 4; nf++) {
                int d = wN * 32 + nf * 8 + 2 * c;
                float b0 = bias[colbase + d], b1 = bias[colbase + d + 1];
                float* o0 = out + (((size_t)bb * H_ + h) * N_ + nbase + rl) * HD + d;
                float* o1 = out + (((size_t)bb * H_ + h) * N_ + nbase + rl + 8) * HD + d;
                *reinterpret_cast<float2*>(o0) =
                    make_float2(f2tff((acc[mf][nf][0] + b0) * sc), f2tff((acc[mf][nf][1] + b1) * sc));
                *reinterpret_cast<float2*>(o1) =
                    make_float2(f2tff((acc[mf][nf][2] + b0) * sc), f2tff((acc[mf][nf][3] + b1) * sc));
            }
        }
    } else {
        __syncthreads();
        float* tb = (float*)sA;   // [64][65]
        #pragma unroll
        for (int mf = 0; mf < 2; mf++) {
            int rl = wM * 32 + mf * 16 + g;
            #pragma unroll
            for (int nf = 0; nf < 4; nf++) {
                int d = wN * 32 + nf * 8 + 2 * c;
                float b0 = bias[colbase + d], b1 = bias[colbase + d + 1];
                tb[d * 65 + rl]           = f2tff(acc[mf][nf][0] + b0);
                tb[(d + 1) * 65 + rl]     = f2tff(acc[mf][nf][1] + b1);
                tb[d * 65 + rl + 8]       = f2tff(acc[mf][nf][2] + b0);
                tb[(d + 1) * 65 + rl + 8] = f2tff(acc[mf][nf][3] + b1);
            }
        }
        __syncthreads();
        #pragma unroll
        for (int p = 0; p < 8; p++) {
            int idx = tid + p * 128;
            int d = idx >> 4, n4 = idx & 15;
            float4 val = make_float4(tb[d * 65 + n4 * 4],     tb[d * 65 + n4 * 4 + 1],
                                     tb[d * 65 + n4 * 4 + 2], tb[d * 65 + n4 * 4 + 3]);
            *reinterpret_cast<float4*>(
                V + (((size_t)bb * H_ + h) * HD + d) * N_ + nbase + n4 * 4) = val;
        }
    }
}

// ============================================================================
// Flash attention (round-9 verbatim): 128 q/CTA, 4 warps x 32 q-rows,
// 64-key tiles, joint-mf QK/PV, P via warp-private smem, ldmatrix everywhere.
// smem words: Ks 2*4352, Vs 2*4352, Ps 4*2176=8704, ms 128  -> 26240 (102.5 KB)
// ============================================================================
#define AKS(buf) ((buf) * 4352)
#define AVS(buf) (8704 + (buf) * 4352)
#define APS      17408
#define AMS      26112
#define ATTN_SMB (26240 * 4)

__global__ __launch_bounds__(128, 2) void attn_t(
    const float* __restrict__ Q, const float* __restrict__ K,
    const float* __restrict__ Vt, const int* __restrict__ mask,
    float* __restrict__ O)
{
    extern __shared__ uint32_t sm[];
    float* ms = (float*)(sm + AMS);
    uint32_t sb = (uint32_t)__cvta_generic_to_shared(sm);

    int bh = blockIdx.y, b = bh >> 3;
    int qbase = blockIdx.x * 128;
    int tid = threadIdx.x, wid = tid >> 5, lane = tid & 31;
    int g = lane >> 2, c = lane & 3;
    int r0 = qbase + wid * 32 + g;
    const size_t kvb = (size_t)bh * N_ * HD;

    int sel = lane >> 3, l8 = lane & 7;
    uint32_t ofB = (uint32_t)((((sel >> 1) * 8 + l8) * 68 + (sel & 1) * 4) * 4);
    uint32_t ofA = (uint32_t)((((sel & 1) * 8 + l8) * 68 + (sel >> 1) * 4) * 4);
    uint32_t pbase = sb + (uint32_t)((APS + wid * 2176) * 4) + ofA;

    uint32_t qf[2][8][4];
    #pragma unroll
    for (int mf = 0; mf < 2; mf++) {
        const uint32_t* Qp = reinterpret_cast<const uint32_t*>(
            Q + ((size_t)bh * N_ + r0 + 16 * mf) * HD);
        #pragma unroll
        for (int ks = 0; ks < 8; ks++) {
            qf[mf][ks][0] = Qp[ks * 8 + c];
            qf[mf][ks][1] = Qp[8 * HD + ks * 8 + c];
            qf[mf][ks][2] = Qp[ks * 8 + c + 4];
            qf[mf][ks][3] = Qp[8 * HD + ks * 8 + c + 4];
        }
    }

    #pragma unroll
    for (int p = 0; p < 8; p++) {
        int idx = tid + p * 128;
        int key = idx >> 4, d4 = idx & 15;
        cp16(sb + (uint32_t)(AKS(0) + key * 68 + d4 * 4) * 4,
             K + kvb + (size_t)key * HD + d4 * 4);
    }
    #pragma unroll
    for (int p = 0; p < 8; p++) {
        int idx = tid + p * 128;
        int d = idx >> 4, k4 = idx & 15;
        cp16(sb + (uint32_t)(AVS(0) + d * 68 + k4 * 4) * 4,
             Vt + kvb + (size_t)d * N_ + k4 * 4);
    }
    CPCOMMIT();
    if (tid < 64) ms[tid] = mask[b * N_ + tid] ? 0.0f : -10000.0f;

    float of[2][8][4] = {};
    float mx[4] = {-1e30f, -1e30f, -1e30f, -1e30f};
    float lsum[4] = {};

    for (int t = 0; t < 32; t++) {
        int buf = t & 1;
        CPWAIT0();
        __syncthreads();
        int mreg = 0;
        if (t < 31) {
            int kn = (t + 1) * 64;
            #pragma unroll
            for (int p = 0; p < 8; p++) {
                int idx = tid + p * 128;
                int key = idx >> 4, d4 = idx & 15;
                cp16(sb + (uint32_t)(AKS(buf ^ 1) + key * 68 + d4 * 4) * 4,
                     K + kvb + (size_t)(kn + key) * HD + d4 * 4);
            }
            #pragma unroll
            for (int p = 0; p < 8; p++) {
                int idx = tid + p * 128;
                int d = idx >> 4, k4 = idx & 15;
                cp16(sb + (uint32_t)(AVS(buf ^ 1) + d * 68 + k4 * 4) * 4,
                     Vt + kvb + (size_t)d * N_ + kn + k4 * 4);
            }
            CPCOMMIT();
            if (tid < 64) mreg = mask[b * N_ + kn + tid];
        }

        uint32_t kb = sb + (uint32_t)(AKS(buf) * 4) + ofB;
        float sacc[2][8][4] = {};
        #pragma unroll
        for (int ks = 0; ks < 8; ks++) {
            #pragma unroll
            for (int p = 0; p < 4; p++) {
                uint32_t b0, b1, b2, b3;
                ldsm4(b0, b1, b2, b3, kb + (uint32_t)((p * 1088 + ks * 8) * 4));
                #pragma unroll
                for (int mf = 0; mf < 2; mf++) {
                    mma_tf32(sacc[mf][2*p],   qf[mf][ks][0], qf[mf][ks][1],
                             qf[mf][ks][2], qf[mf][ks][3], b0, b1);
                    mma_tf32(sacc[mf][2*p+1], qf[mf][ks][0], qf[mf][ks][1],
                             qf[mf][ks][2], qf[mf][ks][3], b2, b3);
                }
            }
        }

        const float* msp = ms + buf * 64;
        #pragma unroll
        for (int mf = 0; mf < 2; mf++) {
            float t0 = -1e30f, t1 = -1e30f;
            #pragma unroll
            for (int nf = 0; nf < 8; nf++) {
                float ma = msp[nf * 8 + 2 * c], mb = msp[nf * 8 + 2 * c + 1];
                sacc[mf][nf][0] += ma; sacc[mf][nf][1] += mb;
                sacc[mf][nf][2] += ma; sacc[mf][nf][3] += mb;
                t0 = fmaxf(t0, fmaxf(sacc[mf][nf][0], sacc[mf][nf][1]));
                t1 = fmaxf(t1, fmaxf(sacc[mf][nf][2], sacc[mf][nf][3]));
            }
            t0 = fmaxf(t0, __shfl_xor_sync(~0u, t0, 1));
            t0 = fmaxf(t0, __shfl_xor_sync(~0u, t0, 2));
            t1 = fmaxf(t1, __shfl_xor_sync(~0u, t1, 1));
            t1 = fmaxf(t1, __shfl_xor_sync(~0u, t1, 2));
            float mn0 = fmaxf(mx[mf*2],   t0);
            float mn1 = fmaxf(mx[mf*2+1], t1);
            if (mn0 > mx[mf*2] || mn1 > mx[mf*2+1]) {
                float co0 = __expf(mx[mf*2] - mn0), co1 = __expf(mx[mf*2+1] - mn1);
                lsum[mf*2] *= co0; lsum[mf*2+1] *= co1;
                #pragma unroll
                for (int nf = 0; nf < 8; nf++) {
                    of[mf][nf][0] *= co0; of[mf][nf][1] *= co0;
                    of[mf][nf][2] *= co1; of[mf][nf][3] *= co1;
                }
                mx[mf*2] = mn0; mx[mf*2+1] = mn1;
            }
        }

        uint32_t* Ps = sm + APS + wid * 2176;
        #pragma unroll
        for (int mf = 0; mf < 2; mf++) {
            int rl = 16 * mf + g;
            #pragma unroll
            for (int nf = 0; nf < 8; nf++) {
                float p0 = __expf(sacc[mf][nf][0] - mx[mf*2]);
                float p1 = __expf(sacc[mf][nf][1] - mx[mf*2]);
                float p2 = __expf(sacc[mf][nf][2] - mx[mf*2+1]);
                float p3 = __expf(sacc[mf][nf][3] - mx[mf*2+1]);
                lsum[mf*2]   += p0 + p1;
                lsum[mf*2+1] += p2 + p3;
                *reinterpret_cast<uint2*>(&Ps[rl * 68 + nf * 8 + 2 * c]) =
                    make_uint2(f2tf(p0), f2tf(p1));
                *reinterpret_cast<uint2*>(&Ps[(rl + 8) * 68 + nf * 8 + 2 * c]) =
                    make_uint2(f2tf(p2), f2tf(p3));
            }
        }
        __syncwarp();

        uint32_t vb = sb + (uint32_t)(AVS(buf) * 4) + ofB;
        #pragma unroll
        for (int ks = 0; ks < 8; ks++) {
            uint32_t a[2][4];
            ldsm4(a[0][0], a[0][1], a[0][2], a[0][3], pbase + (uint32_t)(ks * 32));
            ldsm4(a[1][0], a[1][1], a[1][2], a[1][3],
                  pbase + (uint32_t)(16 * 68 * 4 + ks * 32));
            #pragma unroll
            for (int p = 0; p < 4; p++) {
                uint32_t b0, b1, b2, b3;
                ldsm4(b0, b1, b2, b3, vb + (uint32_t)((p * 1088 + ks * 8) * 4));
                #pragma unroll
                for (int mf = 0; mf < 2; mf++) {
                    mma_tf32(of[mf][2*p],   a[mf][0], a[mf][1], a[mf][2], a[mf][3], b0, b1);
                    mma_tf32(of[mf][2*p+1], a[mf][0], a[mf][1], a[mf][2], a[mf][3], b2, b3);
                }
            }
        }
        if (t < 31 && tid < 64)
            ms[(buf ^ 1) * 64 + tid] = mreg ? 0.0f : -10000.0f;
    }

    #pragma unroll
    for (int i = 0; i < 4; i++) {
        lsum[i] += __shfl_xor_sync(~0u, lsum[i], 1);
        lsum[i] += __shfl_xor_sync(~0u, lsum[i], 2);
    }
    #pragma unroll
    for (int mf = 0; mf < 2; mf++) {
        float inv0 = 1.0f / lsum[mf*2], inv1 = 1.0f / lsum[mf*2+1];
        float* Op = O + ((size_t)bh * N_ + r0 + 16 * mf) * HD;
        #pragma unroll
        for (int nf = 0; nf < 8; nf++) {
            int d = nf * 8 + 2 * c;
            *reinterpret_cast<float2*>(Op + d) =
                make_float2(f2tff(of[mf][nf][0] * inv0), f2tff(of[mf][nf][1] * inv0));
            *reinterpret_cast<float2*>(Op + 8 * HD + d) =
                make_float2(f2tff(of[mf][nf][2] * inv1), f2tff(of[mf][nf][3] * inv1));
        }
    }
}

// ---------------- Output projection (ldsm fragments) --------------------------
__global__ __launch_bounds__(128) void out_gemm(
    const float* __restrict__ AO, const float* __restrict__ bias, float* __restrict__ out)
{
    __shared__ __align__(16) uint32_t sA[2 * 2304];
    __shared__ __align__(16) uint32_t sB[2 * 2304];
    uint32_t aB = (uint32_t)__cvta_generic_to_shared(sA);
    uint32_t bB = (uint32_t)__cvta_generic_to_shared(sB);
    const float* Wt = &g_wt[3][0];

    int tid = threadIdx.x, lane = tid & 31, wid = tid >> 5;
    int wM = wid >> 1, wN = wid & 1, g = lane >> 2, c = lane & 3;
    int rowbase = blockIdx.y * 64, colbase = blockIdx.x * 64;
    int bb = rowbase >> 11, nbase = rowbase & (N_ - 1);

    int sel = lane >> 3, l8 = lane & 7;
    uint32_t ofAg = (uint32_t)((((sel & 1) * 8 + l8) * 36 + (sel >> 1) * 4) * 4);
    uint32_t ofBg = (uint32_t)((((sel >> 1) * 8 + l8) * 36 + (sel & 1) * 4) * 4);

    #pragma unroll
    for (int p = 0; p < 4; p++) {
        int idx = tid + p * 128;
        int r = idx >> 3, k4 = idx & 7;
        int k = k4 * 4, h = k >> 6, d = k & 63;
        uint32_t off = (uint32_t)(r * 36 + k4 * 4) * 4;
        cp16(aB + off, AO + (((size_t)bb * H_ + h) * N_ + nbase + r) * HD + d);
        cp16(bB + off, Wt + (size_t)(colbase + r) * C_ + k4 * 4);
    }
    CPCOMMIT();

    float acc[2][4][4] = {};
    for (int t = 0; t < 16; t++) {
        int buf = t & 1;
        CPWAIT0();
        __syncthreads();
        if (t < 15) {
            int k0 = (t + 1) * 32;
            uint32_t bo = (uint32_t)((buf ^ 1) * 2304) * 4;
            #pragma unroll
            for (int p = 0; p < 4; p++) {
                int idx = tid + p * 128;
                int r = idx >> 3, k4 = idx & 7;
                int k = k0 + k4 * 4, h = k >> 6, d = k & 63;
                uint32_t off = bo + (uint32_t)(r * 36 + k4 * 4) * 4;
                cp16(aB + off, AO + (((size_t)bb * H_ + h) * N_ + nbase + r) * HD + d);
                cp16(bB + off, Wt + (size_t)(colbase + r) * C_ + k0 + k4 * 4);
            }
            CPCOMMIT();
        }
        gemm_frag_compute(aB, bB, buf, wM, wN, ofAg, ofBg, acc);
    }

    #pragma unroll
    for (int mf = 0; mf < 2; mf++) {
        int r = rowbase + wM * 32 + mf * 16 + g;
        #pragma unroll
        for (int nf = 0; nf < 4; nf++) {
            int cc = colbase + wN * 32 + nf * 8 + 2 * c;
            float b0 = bias[cc], b1 = bias[cc + 1];
            *reinterpret_cast<float2*>(out + (size_t)r * C_ + cc) =
                make_float2(acc[mf][nf][0] + b0, acc[mf][nf][1] + b1);
            *reinterpret_cast<float2*>(out + (size_t)(r + 8) * C_ + cc) =
                make_float2(acc[mf][nf][2] + b0, acc[mf][nf][3] + b1);
        }
    }
}

// ---------------- launch -------------------------------------------------------
extern "C" void kernel_launch(void* const* d_in, const int* in_sizes, int n_in,
                              void* d_out, int out_size)
{
    const float* x    = (const float*)d_in[0];
    const int*   mask = (const int*)  d_in[1];
    const float* ln_g = (const float*)d_in[2];
    const float* ln_b = (const float*)d_in[3];
    const float* wq   = (const float*)d_in[4];
    const float* bq   = (const float*)d_in[5];
    const float* wk   = (const float*)d_in[6];
    const float* bk   = (const float*)d_in[7];
    const float* wv   = (const float*)d_in[8];
    const float* bv   = (const float*)d_in[9];
    const float* wo   = (const float*)d_in[10];
    const float* bo   = (const float*)d_in[11];
    float* out = (float*)d_out;

    float *xn, *q, *k, *v, *ao;
    cudaGetSymbolAddress((void**)&xn, g_xn);
    cudaGetSymbolAddress((void**)&q,  g_q);
    cudaGetSymbolAddress((void**)&k,  g_k);
    cudaGetSymbolAddress((void**)&v,  g_v);
    cudaGetSymbolAddress((void**)&ao, g_ao);

    cudaFuncSetAttribute(attn_t, cudaFuncAttributeMaxDynamicSharedMemorySize, ATTN_SMB);

    prep_w<<<dim3(16, 16, 4), 256>>>(wq, wk, wv, wo);
    ln_kernel<<<BN_, 128>>>(x, ln_g, ln_b, xn);
    qkv_gemm<<<dim3(C_ / 64, BN_ / 64, 3), 128>>>(xn, bq, bk, bv, q, k, v);
    attn_t<<<dim3(N_ / 128, BH_), 128, ATTN_SMB>>>(q, k, v, mask, ao);
    out_gemm<<<dim3(C_ / 64, BN_ / 64), 128>>>(ao, bo, out);
}

// round 12
// speedup vs baseline: 1.4608x; 1.3503x over previous
#include <cuda_runtime.h>
#include <cuda_fp16.h>
#include <stdint.h>

#define B_  2
#define N_  2048
#define C_  512
#define H_  8
#define HD  64
#define BN_ (B_*N_)
#define BH_ (B_*H_)
#define SCALE 0.04419417382415922f

__device__ float  g_xn[(size_t)BN_ * C_];
__device__ __half g_q [(size_t)BH_ * N_ * HD];   // [b,h,n,d] scaled fp16
__device__ __half g_k [(size_t)BH_ * N_ * HD];   // [b,h,n,d] fp16
__device__ __half g_v [(size_t)BH_ * N_ * HD];   // [b,h,d,n] transposed fp16
__device__ float  g_ao[(size_t)BH_ * N_ * HD];   // [b,h,n,d] tf32
__device__ float  g_wt[4][(size_t)C_ * C_];      // transposed [n][k] tf32

__device__ __forceinline__ uint32_t f2tf(float f) {
    uint32_t u; asm("cvt.rna.tf32.f32 %0, %1;" : "=r"(u) : "f"(f)); return u;
}
__device__ __forceinline__ float f2tff(float f) { return __uint_as_float(f2tf(f)); }

__device__ __forceinline__ void mma_tf32(float c[4],
    uint32_t a0, uint32_t a1, uint32_t a2, uint32_t a3, uint32_t b0, uint32_t b1)
{
    asm volatile(
        "mma.sync.aligned.m16n8k8.row.col.f32.tf32.tf32.f32 "
        "{%0,%1,%2,%3}, {%4,%5,%6,%7}, {%8,%9}, {%0,%1,%2,%3};"
        : "+f"(c[0]), "+f"(c[1]), "+f"(c[2]), "+f"(c[3])
        : "r"(a0), "r"(a1), "r"(a2), "r"(a3), "r"(b0), "r"(b1));
}
__device__ __forceinline__ void mma_f16(float c[4],
    uint32_t a0, uint32_t a1, uint32_t a2, uint32_t a3, uint32_t b0, uint32_t b1)
{
    asm volatile(
        "mma.sync.aligned.m16n8k16.row.col.f32.f16.f16.f32 "
        "{%0,%1,%2,%3}, {%4,%5,%6,%7}, {%8,%9}, {%0,%1,%2,%3};"
        : "+f"(c[0]), "+f"(c[1]), "+f"(c[2]), "+f"(c[3])
        : "r"(a0), "r"(a1), "r"(a2), "r"(a3), "r"(b0), "r"(b1));
}
__device__ __forceinline__ void ldsm4(uint32_t& r0, uint32_t& r1, uint32_t& r2,
                                      uint32_t& r3, uint32_t a)
{
    asm volatile("ldmatrix.sync.aligned.m8n8.x4.shared.b16 {%0,%1,%2,%3}, [%4];"
        : "=r"(r0), "=r"(r1), "=r"(r2), "=r"(r3) : "r"(a));
}
__device__ __forceinline__ void cp16(uint32_t dst, const void* src) {
    asm volatile("cp.async.cg.shared.global [%0], [%1], 16;" :: "r"(dst), "l"(src));
}
#define CPCOMMIT() asm volatile("cp.async.commit_group;")
#define CPWAIT0()  asm volatile("cp.async.wait_group 0;")

// ---------------- weight prep: transpose + tf32 round -------------------------
__global__ __launch_bounds__(256) void prep_w(
    const float* __restrict__ wq, const float* __restrict__ wk,
    const float* __restrict__ wv, const float* __restrict__ wo)
{
    __shared__ float tile[32][33];
    int m = blockIdx.z;
    const float* s = (m == 0) ? wq : (m == 1) ? wk : (m == 2) ? wv : wo;
    int x0 = blockIdx.x * 32, y0 = blockIdx.y * 32;
    int tx = threadIdx.x & 31, ty = threadIdx.x >> 5;
    #pragma unroll
    for (int i = 0; i < 4; i++)
        tile[ty + 8 * i][tx] = s[(size_t)(y0 + ty + 8 * i) * C_ + x0 + tx];
    __syncthreads();
    #pragma unroll
    for (int i = 0; i < 4; i++)
        g_wt[m][(size_t)(x0 + ty + 8 * i) * C_ + y0 + tx] = f2tff(tile[tx][ty + 8 * i]);
}

// ---------------- LayerNorm (tf32-rounded output) ----------------------------
__global__ __launch_bounds__(128) void ln_kernel(
    const float* __restrict__ x, const float* __restrict__ g,
    const float* __restrict__ bta, float* __restrict__ xn)
{
    int row = blockIdx.x, tid = threadIdx.x;
    float4 v = reinterpret_cast<const float4*>(x + (size_t)row * C_)[tid];
    float s = v.x + v.y + v.z + v.w;
    float ss = v.x*v.x + v.y*v.y + v.z*v.z + v.w*v.w;
    #pragma unroll
    for (int o = 16; o; o >>= 1) {
        s  += __shfl_xor_sync(~0u, s,  o);
        ss += __shfl_xor_sync(~0u, ss, o);
    }
    __shared__ float sh[8];
    int w = tid >> 5, l = tid & 31;
    if (l == 0) { sh[w] = s; sh[4 + w] = ss; }
    __syncthreads();
    float st = sh[0]+sh[1]+sh[2]+sh[3], sst = sh[4]+sh[5]+sh[6]+sh[7];
    float mean = st * (1.0f / C_);
    float var  = sst * (1.0f / C_) - mean * mean;
    float r = rsqrtf(var + 1e-5f);
    float4 gg = reinterpret_cast<const float4*>(g)[tid];
    float4 bb = reinterpret_cast<const float4*>(bta)[tid];
    float4 o;
    o.x = f2tff((v.x - mean) * r * gg.x + bb.x);
    o.y = f2tff((v.y - mean) * r * gg.y + bb.y);
    o.z = f2tff((v.z - mean) * r * gg.z + bb.z);
    o.w = f2tff((v.w - mean) * r * gg.w + bb.w);
    reinterpret_cast<float4*>(xn + (size_t)row * C_)[tid] = o;
}

// ============================================================================
// GEMM (round-11 verified): 64x64 tile, BK=32, 128 thr, tf32 + ldsm fragments.
// ============================================================================
__device__ __forceinline__ void gemm_frag_compute(
    uint32_t aBase, uint32_t bBase, int buf, int wM, int wN,
    uint32_t ofAg, uint32_t ofBg, float acc[2][4][4])
{
    #pragma unroll
    for (int ks = 0; ks < 4; ks++) {
        uint32_t a[2][4], b[4][2];
        #pragma unroll
        for (int mf = 0; mf < 2; mf++)
            ldsm4(a[mf][0], a[mf][1], a[mf][2], a[mf][3],
                  aBase + (uint32_t)((buf * 2304 + (wM * 32 + mf * 16) * 36 + ks * 8) * 4) + ofAg);
        #pragma unroll
        for (int p = 0; p < 2; p++) {
            uint32_t b0, b1, b2, b3;
            ldsm4(b0, b1, b2, b3,
                  bBase + (uint32_t)((buf * 2304 + (wN * 32 + p * 16) * 36 + ks * 8) * 4) + ofBg);
            b[2*p][0] = b0; b[2*p][1] = b1;
            b[2*p+1][0] = b2; b[2*p+1][1] = b3;
        }
        #pragma unroll
        for (int mf = 0; mf < 2; mf++)
            #pragma unroll
            for (int nf = 0; nf < 4; nf++)
                mma_tf32(acc[mf][nf], a[mf][0], a[mf][1], a[mf][2], a[mf][3],
                         b[nf][0], b[nf][1]);
    }
}

__global__ __launch_bounds__(128) void qkv_gemm(
    const float* __restrict__ A,
    const float* __restrict__ bq, const float* __restrict__ bk, const float* __restrict__ bv,
    __half* __restrict__ Q, __half* __restrict__ K, __half* __restrict__ V)
{
    __shared__ __align__(16) uint32_t sA[2 * 2304];
    __shared__ __align__(16) uint32_t sB[2 * 2304];
    uint32_t aB = (uint32_t)__cvta_generic_to_shared(sA);
    uint32_t bB = (uint32_t)__cvta_generic_to_shared(sB);

    int z = blockIdx.z;
    const float* Wt = &g_wt[z][0];
    const float* bias = (z == 0) ? bq : (z == 1) ? bk : bv;

    int tid = threadIdx.x, lane = tid & 31, wid = tid >> 5;
    int wM = wid >> 1, wN = wid & 1, g = lane >> 2, c = lane & 3;
    int rowbase = blockIdx.y * 64, colbase = blockIdx.x * 64;

    int sel = lane >> 3, l8 = lane & 7;
    uint32_t ofAg = (uint32_t)((((sel & 1) * 8 + l8) * 36 + (sel >> 1) * 4) * 4);
    uint32_t ofBg = (uint32_t)((((sel >> 1) * 8 + l8) * 36 + (sel & 1) * 4) * 4);

    #pragma unroll
    for (int p = 0; p < 4; p++) {
        int idx = tid + p * 128;
        int r = idx >> 3, k4 = idx & 7;
        uint32_t off = (uint32_t)(r * 36 + k4 * 4) * 4;
        cp16(aB + off, A  + (size_t)(rowbase + r) * C_ + k4 * 4);
        cp16(bB + off, Wt + (size_t)(colbase + r) * C_ + k4 * 4);
    }
    CPCOMMIT();

    float acc[2][4][4] = {};
    for (int t = 0; t < 16; t++) {
        int buf = t & 1;
        CPWAIT0();
        __syncthreads();
        if (t < 15) {
            int k0 = (t + 1) * 32;
            uint32_t bo = (uint32_t)((buf ^ 1) * 2304) * 4;
            #pragma unroll
            for (int p = 0; p < 4; p++) {
                int idx = tid + p * 128;
                int r = idx >> 3, k4 = idx & 7;
                uint32_t off = bo + (uint32_t)(r * 36 + k4 * 4) * 4;
                cp16(aB + off, A  + (size_t)(rowbase + r) * C_ + k0 + k4 * 4);
                cp16(bB + off, Wt + (size_t)(colbase + r) * C_ + k0 + k4 * 4);
            }
            CPCOMMIT();
        }
        gemm_frag_compute(aB, bB, buf, wM, wN, ofAg, ofBg, acc);
    }

    int h = blockIdx.x;
    int bb = rowbase >> 11, nbase = rowbase & (N_ - 1);
    if (z != 2) {
        __half* out = z ? K : Q;
        float sc = z ? 1.0f : SCALE;
        #pragma unroll
        for (int mf = 0; mf < 2; mf++) {
            int rl = wM * 32 + mf * 16 + g;
            #pragma unroll
            for (int nf = 0; nf < 4; nf++) {
                int d = wN * 32 + nf * 8 + 2 * c;
                float b0 = bias[colbase + d], b1 = bias[colbase + d + 1];
                __half2* o0 = reinterpret_cast<__half2*>(
                    out + (((size_t)bb * H_ + h) * N_ + nbase + rl) * HD + d);
                __half2* o1 = reinterpret_cast<__half2*>(
                    out + (((size_t)bb * H_ + h) * N_ + nbase + rl + 8) * HD + d);
                *o0 = __floats2half2_rn((acc[mf][nf][0] + b0) * sc, (acc[mf][nf][1] + b1) * sc);
                *o1 = __floats2half2_rn((acc[mf][nf][2] + b0) * sc, (acc[mf][nf][3] + b1) * sc);
            }
        }
    } else {
        __syncthreads();
        float* tb = (float*)sA;   // [64][65]
        #pragma unroll
        for (int mf = 0; mf < 2; mf++) {
            int rl = wM * 32 + mf * 16 + g;
            #pragma unroll
            for (int nf = 0; nf < 4; nf++) {
                int d = wN * 32 + nf * 8 + 2 * c;
                float b0 = bias[colbase + d], b1 = bias[colbase + d + 1];
                tb[d * 65 + rl]           = acc[mf][nf][0] + b0;
                tb[(d + 1) * 65 + rl]     = acc[mf][nf][1] + b1;
                tb[d * 65 + rl + 8]       = acc[mf][nf][2] + b0;
                tb[(d + 1) * 65 + rl + 8] = acc[mf][nf][3] + b1;
            }
        }
        __syncthreads();
        #pragma unroll
        for (int p = 0; p < 8; p++) {
            int idx = tid + p * 128;
            int d = idx >> 4, n4 = idx & 15;
            __half2 v0 = __floats2half2_rn(tb[d * 65 + n4 * 4],     tb[d * 65 + n4 * 4 + 1]);
            __half2 v1 = __floats2half2_rn(tb[d * 65 + n4 * 4 + 2], tb[d * 65 + n4 * 4 + 3]);
            uint2 st = make_uint2(*reinterpret_cast<uint32_t*>(&v0),
                                  *reinterpret_cast<uint32_t*>(&v1));
            *reinterpret_cast<uint2*>(
                V + (((size_t)bb * H_ + h) * HD + d) * N_ + nbase + n4 * 4) = st;
        }
    }
}

// ============================================================================
// Flash attention fp16: 128 q/CTA, 4 warps x 32 q-rows, 64-key tiles.
// Tiles: rows of 64 fp16 = 128B, stride 144B. mma.m16n8k16.f16, fp32 accum.
// smem bytes: Ks 2*9216, Vs 2*9216, Ps 4*4608, ms 512  -> 55808 (54.5 KB)
// ============================================================================
#define AKSB(buf) ((buf) * 9216)
#define AVSB(buf) (18432 + (buf) * 9216)
#define APSB      36864
#define AMSB      55296
#define ATTN_SMB  55808

__global__ __launch_bounds__(128, 2) void attn_t(
    const __half* __restrict__ Q, const __half* __restrict__ K,
    const __half* __restrict__ Vt, const int* __restrict__ mask,
    float* __restrict__ O)
{
    extern __shared__ char smc[];
    float* ms = (float*)(smc + AMSB);
    uint32_t sb = (uint32_t)__cvta_generic_to_shared(smc);

    int bh = blockIdx.y, b = bh >> 3;
    int qbase = blockIdx.x * 128;
    int tid = threadIdx.x, wid = tid >> 5, lane = tid & 31;
    int g = lane >> 2, c = lane & 3;
    int r0 = qbase + wid * 32 + g;
    const size_t kvb = (size_t)bh * N_ * HD;

    int sel = lane >> 3, l8 = lane & 7;
    uint32_t ofB = (uint32_t)(((sel >> 1) * 8 + l8) * 144 + (sel & 1) * 16);
    uint32_t ofA = (uint32_t)(((sel & 1) * 8 + l8) * 144 + (sel >> 1) * 16);
    uint32_t pbase = sb + (uint32_t)(APSB + wid * 4608) + ofA;

    // Q fragments: fp16 packed, 2 m-frags x 4 k-steps x 4 regs
    uint32_t qf[2][4][4];
    #pragma unroll
    for (int mf = 0; mf < 2; mf++) {
        const uint32_t* Qp = reinterpret_cast<const uint32_t*>(
            Q + ((size_t)bh * N_ + r0 + 16 * mf) * HD);
        #pragma unroll
        for (int ks = 0; ks < 4; ks++) {
            qf[mf][ks][0] = Qp[ks * 8 + c];
            qf[mf][ks][1] = Qp[256 + ks * 8 + c];
            qf[mf][ks][2] = Qp[ks * 8 + 4 + c];
            qf[mf][ks][3] = Qp[256 + ks * 8 + 4 + c];
        }
    }

    #pragma unroll
    for (int p = 0; p < 4; p++) {
        int idx = tid + p * 128;
        int key = idx >> 3, d8 = idx & 7;
        cp16(sb + (uint32_t)(AKSB(0) + key * 144 + d8 * 16),
             K + kvb + (size_t)key * HD + d8 * 8);
    }
    #pragma unroll
    for (int p = 0; p < 4; p++) {
        int idx = tid + p * 128;
        int d = idx >> 3, k8 = idx & 7;
        cp16(sb + (uint32_t)(AVSB(0) + d * 144 + k8 * 16),
             Vt + kvb + (size_t)d * N_ + k8 * 8);
    }
    CPCOMMIT();
    if (tid < 64) ms[tid] = mask[b * N_ + tid] ? 0.0f : -10000.0f;

    float of[2][8][4] = {};
    float mx[4] = {-1e30f, -1e30f, -1e30f, -1e30f};
    float lsum[4] = {};

    for (int t = 0; t < 32; t++) {
        int buf = t & 1;
        CPWAIT0();
        __syncthreads();
        int mreg = 0;
        if (t < 31) {
            int kn = (t + 1) * 64;
            #pragma unroll
            for (int p = 0; p < 4; p++) {
                int idx = tid + p * 128;
                int key = idx >> 3, d8 = idx & 7;
                cp16(sb + (uint32_t)(AKSB(buf ^ 1) + key * 144 + d8 * 16),
                     K + kvb + (size_t)(kn + key) * HD + d8 * 8);
            }
            #pragma unroll
            for (int p = 0; p < 4; p++) {
                int idx = tid + p * 128;
                int d = idx >> 3, k8 = idx & 7;
                cp16(sb + (uint32_t)(AVSB(buf ^ 1) + d * 144 + k8 * 16),
                     Vt + kvb + (size_t)d * N_ + kn + k8 * 8);
            }
            CPCOMMIT();
            if (tid < 64) mreg = mask[b * N_ + kn + tid];
        }

        // S = Q K^T  (4 k-steps of 16; B ldsm.x4 covers 2 nf blocks)
        uint32_t kb = sb + (uint32_t)AKSB(buf) + ofB;
        float sacc[2][8][4] = {};
        #pragma unroll
        for (int ks = 0; ks < 4; ks++) {
            #pragma unroll
            for (int p = 0; p < 4; p++) {
                uint32_t b0, b1, b2, b3;
                ldsm4(b0, b1, b2, b3, kb + (uint32_t)(p * 2304 + ks * 32));
                #pragma unroll
                for (int mf = 0; mf < 2; mf++) {
                    mma_f16(sacc[mf][2*p],   qf[mf][ks][0], qf[mf][ks][1],
                            qf[mf][ks][2], qf[mf][ks][3], b0, b1);
                    mma_f16(sacc[mf][2*p+1], qf[mf][ks][0], qf[mf][ks][1],
                            qf[mf][ks][2], qf[mf][ks][3], b2, b3);
                }
            }
        }

        // mask + online softmax
        const float* msp = ms + buf * 64;
        #pragma unroll
        for (int mf = 0; mf < 2; mf++) {
            float t0 = -1e30f, t1 = -1e30f;
            #pragma unroll
            for (int nf = 0; nf < 8; nf++) {
                float ma = msp[nf * 8 + 2 * c], mb = msp[nf * 8 + 2 * c + 1];
                sacc[mf][nf][0] += ma; sacc[mf][nf][1] += mb;
                sacc[mf][nf][2] += ma; sacc[mf][nf][3] += mb;
                t0 = fmaxf(t0, fmaxf(sacc[mf][nf][0], sacc[mf][nf][1]));
                t1 = fmaxf(t1, fmaxf(sacc[mf][nf][2], sacc[mf][nf][3]));
            }
            t0 = fmaxf(t0, __shfl_xor_sync(~0u, t0, 1));
            t0 = fmaxf(t0, __shfl_xor_sync(~0u, t0, 2));
            t1 = fmaxf(t1, __shfl_xor_sync(~0u, t1, 1));
            t1 = fmaxf(t1, __shfl_xor_sync(~0u, t1, 2));
            float mn0 = fmaxf(mx[mf*2],   t0);
            float mn1 = fmaxf(mx[mf*2+1], t1);
            if (mn0 > mx[mf*2] || mn1 > mx[mf*2+1]) {
                float co0 = __expf(mx[mf*2] - mn0), co1 = __expf(mx[mf*2+1] - mn1);
                lsum[mf*2] *= co0; lsum[mf*2+1] *= co1;
                #pragma unroll
                for (int nf = 0; nf < 8; nf++) {
                    of[mf][nf][0] *= co0; of[mf][nf][1] *= co0;
                    of[mf][nf][2] *= co1; of[mf][nf][3] *= co1;
                }
                mx[mf*2] = mn0; mx[mf*2+1] = mn1;
            }
        }

        // P -> warp-private smem (fp16 pairs)
        #pragma unroll
        for (int mf = 0; mf < 2; mf++) {
            int rl = 16 * mf + g;
            uint32_t* pr0 = (uint32_t*)(smc + APSB + wid * 4608 + rl * 144);
            uint32_t* pr1 = (uint32_t*)(smc + APSB + wid * 4608 + (rl + 8) * 144);
            #pragma unroll
            for (int nf = 0; nf < 8; nf++) {
                float p0 = __expf(sacc[mf][nf][0] - mx[mf*2]);
                float p1 = __expf(sacc[mf][nf][1] - mx[mf*2]);
                float p2 = __expf(sacc[mf][nf][2] - mx[mf*2+1]);
                float p3 = __expf(sacc[mf][nf][3] - mx[mf*2+1]);
                lsum[mf*2]   += p0 + p1;
                lsum[mf*2+1] += p2 + p3;
                __half2 h0 = __floats2half2_rn(p0, p1);
                __half2 h1 = __floats2half2_rn(p2, p3);
                pr0[nf * 4 + c] = *reinterpret_cast<uint32_t*>(&h0);
                pr1[nf * 4 + c] = *reinterpret_cast<uint32_t*>(&h1);
            }
        }
        __syncwarp();

        // O += P V
        uint32_t vb = sb + (uint32_t)AVSB(buf) + ofB;
        #pragma unroll
        for (int ks = 0; ks < 4; ks++) {
            uint32_t a[2][4];
            ldsm4(a[0][0], a[0][1], a[0][2], a[0][3], pbase + (uint32_t)(ks * 32));
            ldsm4(a[1][0], a[1][1], a[1][2], a[1][3],
                  pbase + (uint32_t)(16 * 144 + ks * 32));
            #pragma unroll
            for (int p = 0; p < 4; p++) {
                uint32_t b0, b1, b2, b3;
                ldsm4(b0, b1, b2, b3, vb + (uint32_t)(p * 2304 + ks * 32));
                #pragma unroll
                for (int mf = 0; mf < 2; mf++) {
                    mma_f16(of[mf][2*p],   a[mf][0], a[mf][1], a[mf][2], a[mf][3], b0, b1);
                    mma_f16(of[mf][2*p+1], a[mf][0], a[mf][1], a[mf][2], a[mf][3], b2, b3);
                }
            }
        }
        if (t < 31 && tid < 64)
            ms[(buf ^ 1) * 64 + tid] = mreg ? 0.0f : -10000.0f;
    }

    #pragma unroll
    for (int i = 0; i < 4; i++) {
        lsum[i] += __shfl_xor_sync(~0u, lsum[i], 1);
        lsum[i] += __shfl_xor_sync(~0u, lsum[i], 2);
    }
    #pragma unroll
    for (int mf = 0; mf < 2; mf++) {
        float inv0 = 1.0f / lsum[mf*2], inv1 = 1.0f / lsum[mf*2+1];
        float* Op = O + ((size_t)bh * N_ + r0 + 16 * mf) * HD;
        #pragma unroll
        for (int nf = 0; nf < 8; nf++) {
            int d = nf * 8 + 2 * c;
            *reinterpret_cast<float2*>(Op + d) =
                make_float2(f2tff(of[mf][nf][0] * inv0), f2tff(of[mf][nf][1] * inv0));
            *reinterpret_cast<float2*>(Op + 8 * HD + d) =
                make_float2(f2tff(of[mf][nf][2] * inv1), f2tff(of[mf][nf][3] * inv1));
        }
    }
}

// ---------------- Output projection (round-11 verified) ------------------------
__global__ __launch_bounds__(128) void out_gemm(
    const float* __restrict__ AO, const float* __restrict__ bias, float* __restrict__ out)
{
    __shared__ __align__(16) uint32_t sA[2 * 2304];
    __shared__ __align__(16) uint32_t sB[2 * 2304];
    uint32_t aB = (uint32_t)__cvta_generic_to_shared(sA);
    uint32_t bB = (uint32_t)__cvta_generic_to_shared(sB);
    const float* Wt = &g_wt[3][0];

    int tid = threadIdx.x, lane = tid & 31, wid = tid >> 5;
    int wM = wid >> 1, wN = wid & 1, g = lane >> 2, c = lane & 3;
    int rowbase = blockIdx.y * 64, colbase = blockIdx.x * 64;
    int bb = rowbase >> 11, nbase = rowbase & (N_ - 1);

    int sel = lane >> 3, l8 = lane & 7;
    uint32_t ofAg = (uint32_t)((((sel & 1) * 8 + l8) * 36 + (sel >> 1) * 4) * 4);
    uint32_t ofBg = (uint32_t)((((sel >> 1) * 8 + l8) * 36 + (sel & 1) * 4) * 4);

    #pragma unroll
    for (int p = 0; p < 4; p++) {
        int idx = tid + p * 128;
        int r = idx >> 3, k4 = idx & 7;
        int k = k4 * 4, h = k >> 6, d = k & 63;
        uint32_t off = (uint32_t)(r * 36 + k4 * 4) * 4;
        cp16(aB + off, AO + (((size_t)bb * H_ + h) * N_ + nbase + r) * HD + d);
        cp16(bB + off, Wt + (size_t)(colbase + r) * C_ + k4 * 4);
    }
    CPCOMMIT();

    float acc[2][4][4] = {};
    for (int t = 0; t < 16; t++) {
        int buf = t & 1;
        CPWAIT0();
        __syncthreads();
        if (t < 15) {
            int k0 = (t + 1) * 32;
            uint32_t bo = (uint32_t)((buf ^ 1) * 2304) * 4;
            #pragma unroll
            for (int p = 0; p < 4; p++) {
                int idx = tid + p * 128;
                int r = idx >> 3, k4 = idx & 7;
                int k = k0 + k4 * 4, h = k >> 6, d = k & 63;
                uint32_t off = bo + (uint32_t)(r * 36 + k4 * 4) * 4;
                cp16(aB + off, AO + (((size_t)bb * H_ + h) * N_ + nbase + r) * HD + d);
                cp16(bB + off, Wt + (size_t)(colbase + r) * C_ + k0 + k4 * 4);
            }
            CPCOMMIT();
        }
        gemm_frag_compute(aB, bB, buf, wM, wN, ofAg, ofBg, acc);
    }

    #pragma unroll
    for (int mf = 0; mf < 2; mf++) {
        int r = rowbase + wM * 32 + mf * 16 + g;
        #pragma unroll
        for (int nf = 0; nf < 4; nf++) {
            int cc = colbase + wN * 32 + nf * 8 + 2 * c;
            float b0 = bias[cc], b1 = bias[cc + 1];
            *reinterpret_cast<float2*>(out + (size_t)r * C_ + cc) =
                make_float2(acc[mf][nf][0] + b0, acc[mf][nf][1] + b1);
            *reinterpret_cast<float2*>(out + (size_t)(r + 8) * C_ + cc) =
                make_float2(acc[mf][nf][2] + b0, acc[mf][nf][3] + b1);
        }
    }
}

// ---------------- launch -------------------------------------------------------
extern "C" void kernel_launch(void* const* d_in, const int* in_sizes, int n_in,
                              void* d_out, int out_size)
{
    const float* x    = (const float*)d_in[0];
    const int*   mask = (const int*)  d_in[1];
    const float* ln_g = (const float*)d_in[2];
    const float* ln_b = (const float*)d_in[3];
    const float* wq   = (const float*)d_in[4];
    const float* bq   = (const float*)d_in[5];
    const float* wk   = (const float*)d_in[6];
    const float* bk   = (const float*)d_in[7];
    const float* wv   = (const float*)d_in[8];
    const float* bv   = (const float*)d_in[9];
    const float* wo   = (const float*)d_in[10];
    const float* bo   = (const float*)d_in[11];
    float* out = (float*)d_out;

    float *xn, *ao;
    __half *q, *k, *v;
    cudaGetSymbolAddress((void**)&xn, g_xn);
    cudaGetSymbolAddress((void**)&q,  g_q);
    cudaGetSymbolAddress((void**)&k,  g_k);
    cudaGetSymbolAddress((void**)&v,  g_v);
    cudaGetSymbolAddress((void**)&ao, g_ao);

    cudaFuncSetAttribute(attn_t, cudaFuncAttributeMaxDynamicSharedMemorySize, ATTN_SMB);

    prep_w<<<dim3(16, 16, 4), 256>>>(wq, wk, wv, wo);
    ln_kernel<<<BN_, 128>>>(x, ln_g, ln_b, xn);
    qkv_gemm<<<dim3(C_ / 64, BN_ / 64, 3), 128>>>(xn, bq, bk, bv, q, k, v);
    attn_t<<<dim3(N_ / 128, BH_), 128, ATTN_SMB>>>(q, k, v, mask, ao);
    out_gemm<<<dim3(C_ / 64, BN_ / 64), 128>>>(ao, bo, out);
}

// round 13
// speedup vs baseline: 1.7884x; 1.2243x over previous
#include <cuda_runtime.h>
#include <cuda_fp16.h>
#include <stdint.h>

#define B_  2
#define N_  2048
#define C_  512
#define H_  8
#define HD  64
#define BN_ (B_*N_)
#define BH_ (B_*H_)
#define SCALE 0.04419417382415922f

__device__ __half g_xn[(size_t)BN_ * C_];        // fp16 LN output
__device__ __half g_q [(size_t)BH_ * N_ * HD];   // [b,h,n,d] scaled fp16
__device__ __half g_k [(size_t)BH_ * N_ * HD];   // [b,h,n,d] fp16
__device__ __half g_v [(size_t)BH_ * N_ * HD];   // [b,h,d,n] transposed fp16
__device__ __half g_ao[(size_t)BH_ * N_ * HD];   // [b,h,n,d] fp16
__device__ __half g_wt[4][(size_t)C_ * C_];      // transposed [n][k] fp16

__device__ __forceinline__ void mma_f16(float c[4],
    uint32_t a0, uint32_t a1, uint32_t a2, uint32_t a3, uint32_t b0, uint32_t b1)
{
    asm volatile(
        "mma.sync.aligned.m16n8k16.row.col.f32.f16.f16.f32 "
        "{%0,%1,%2,%3}, {%4,%5,%6,%7}, {%8,%9}, {%0,%1,%2,%3};"
        : "+f"(c[0]), "+f"(c[1]), "+f"(c[2]), "+f"(c[3])
        : "r"(a0), "r"(a1), "r"(a2), "r"(a3), "r"(b0), "r"(b1));
}
__device__ __forceinline__ void ldsm4(uint32_t& r0, uint32_t& r1, uint32_t& r2,
                                      uint32_t& r3, uint32_t a)
{
    asm volatile("ldmatrix.sync.aligned.m8n8.x4.shared.b16 {%0,%1,%2,%3}, [%4];"
        : "=r"(r0), "=r"(r1), "=r"(r2), "=r"(r3) : "r"(a));
}
__device__ __forceinline__ void cp16(uint32_t dst, const void* src) {
    asm volatile("cp.async.cg.shared.global [%0], [%1], 16;" :: "r"(dst), "l"(src));
}
#define CPCOMMIT() asm volatile("cp.async.commit_group;")
#define CPWAIT0()  asm volatile("cp.async.wait_group 0;")

// ---------------- weight prep: transpose + fp16 round --------------------------
__global__ __launch_bounds__(256) void prep_w(
    const float* __restrict__ wq, const float* __restrict__ wk,
    const float* __restrict__ wv, const float* __restrict__ wo)
{
    __shared__ float tile[32][33];
    int m = blockIdx.z;
    const float* s = (m == 0) ? wq : (m == 1) ? wk : (m == 2) ? wv : wo;
    int x0 = blockIdx.x * 32, y0 = blockIdx.y * 32;
    int tx = threadIdx.x & 31, ty = threadIdx.x >> 5;
    #pragma unroll
    for (int i = 0; i < 4; i++)
        tile[ty + 8 * i][tx] = s[(size_t)(y0 + ty + 8 * i) * C_ + x0 + tx];
    __syncthreads();
    #pragma unroll
    for (int i = 0; i < 4; i++)
        g_wt[m][(size_t)(x0 + ty + 8 * i) * C_ + y0 + tx] = __float2half_rn(tile[tx][ty + 8 * i]);
}

// ---------------- LayerNorm (fp16 output) --------------------------------------
__global__ __launch_bounds__(128) void ln_kernel(
    const float* __restrict__ x, const float* __restrict__ g,
    const float* __restrict__ bta, __half* __restrict__ xn)
{
    int row = blockIdx.x, tid = threadIdx.x;
    float4 v = reinterpret_cast<const float4*>(x + (size_t)row * C_)[tid];
    float s = v.x + v.y + v.z + v.w;
    float ss = v.x*v.x + v.y*v.y + v.z*v.z + v.w*v.w;
    #pragma unroll
    for (int o = 16; o; o >>= 1) {
        s  += __shfl_xor_sync(~0u, s,  o);
        ss += __shfl_xor_sync(~0u, ss, o);
    }
    __shared__ float sh[8];
    int w = tid >> 5, l = tid & 31;
    if (l == 0) { sh[w] = s; sh[4 + w] = ss; }
    __syncthreads();
    float st = sh[0]+sh[1]+sh[2]+sh[3], sst = sh[4]+sh[5]+sh[6]+sh[7];
    float mean = st * (1.0f / C_);
    float var  = sst * (1.0f / C_) - mean * mean;
    float r = rsqrtf(var + 1e-5f);
    float4 gg = reinterpret_cast<const float4*>(g)[tid];
    float4 bb = reinterpret_cast<const float4*>(bta)[tid];
    __half2 h0 = __floats2half2_rn((v.x - mean) * r * gg.x + bb.x,
                                   (v.y - mean) * r * gg.y + bb.y);
    __half2 h1 = __floats2half2_rn((v.z - mean) * r * gg.z + bb.z,
                                   (v.w - mean) * r * gg.w + bb.w);
    uint2 st2 = make_uint2(*reinterpret_cast<uint32_t*>(&h0),
                           *reinterpret_cast<uint32_t*>(&h1));
    *reinterpret_cast<uint2*>(xn + (size_t)row * C_ + tid * 4) = st2;
}

// ============================================================================
// fp16 GEMM: 64x64 CTA tile, BK=64, 128 thr, 4 warps (2Mx2N, warp 32x32).
// Tiles: rows of 64 fp16 = 128B, stride 144B (round-12-verified layout).
// smem: sA 2*9216 B, sB 2*9216 B.
// ============================================================================
__device__ __forceinline__ void gemm_frag_f16(
    uint32_t aBase, uint32_t bBase, int buf, int wM, int wN,
    uint32_t ofA, uint32_t ofB, float acc[2][4][4])
{
    #pragma unroll
    for (int ks = 0; ks < 4; ks++) {
        uint32_t a[2][4];
        #pragma unroll
        for (int mf = 0; mf < 2; mf++)
            ldsm4(a[mf][0], a[mf][1], a[mf][2], a[mf][3],
                  aBase + (uint32_t)(buf * 9216 + (wM * 32 + mf * 16) * 144 + ks * 32) + ofA);
        #pragma unroll
        for (int p = 0; p < 2; p++) {
            uint32_t b0, b1, b2, b3;
            ldsm4(b0, b1, b2, b3,
                  bBase + (uint32_t)(buf * 9216 + (wN * 32 + p * 16) * 144 + ks * 32) + ofB);
            #pragma unroll
            for (int mf = 0; mf < 2; mf++) {
                mma_f16(acc[mf][2*p],   a[mf][0], a[mf][1], a[mf][2], a[mf][3], b0, b1);
                mma_f16(acc[mf][2*p+1], a[mf][0], a[mf][1], a[mf][2], a[mf][3], b2, b3);
            }
        }
    }
}

__global__ __launch_bounds__(128) void qkv_gemm(
    const __half* __restrict__ A,
    const float* __restrict__ bq, const float* __restrict__ bk, const float* __restrict__ bv,
    __half* __restrict__ Q, __half* __restrict__ K, __half* __restrict__ V)
{
    __shared__ __align__(16) char sAc[2 * 9216];
    __shared__ __align__(16) char sBc[2 * 9216];
    uint32_t aB = (uint32_t)__cvta_generic_to_shared(sAc);
    uint32_t bB = (uint32_t)__cvta_generic_to_shared(sBc);

    int z = blockIdx.z;
    const __half* Wt = &g_wt[z][0];
    const float* bias = (z == 0) ? bq : (z == 1) ? bk : bv;

    int tid = threadIdx.x, lane = tid & 31, wid = tid >> 5;
    int wM = wid >> 1, wN = wid & 1, g = lane >> 2, c = lane & 3;
    int rowbase = blockIdx.y * 64, colbase = blockIdx.x * 64;

    int sel = lane >> 3, l8 = lane & 7;
    uint32_t ofA = (uint32_t)(((sel & 1) * 8 + l8) * 144 + (sel >> 1) * 16);
    uint32_t ofB = (uint32_t)(((sel >> 1) * 8 + l8) * 144 + (sel & 1) * 16);

    // prologue: tile 0 into buf 0 (rows of 128B, 8 cp16/row)
    #pragma unroll
    for (int p = 0; p < 4; p++) {
        int idx = tid + p * 128;
        int r = idx >> 3, k8 = idx & 7;
        uint32_t off = (uint32_t)(r * 144 + k8 * 16);
        cp16(aB + off, A  + (size_t)(rowbase + r) * C_ + k8 * 8);
        cp16(bB + off, Wt + (size_t)(colbase + r) * C_ + k8 * 8);
    }
    CPCOMMIT();

    float acc[2][4][4] = {};
    for (int t = 0; t < 8; t++) {
        int buf = t & 1;
        CPWAIT0();
        __syncthreads();
        if (t < 7) {
            int k0 = (t + 1) * 64;
            uint32_t bo = (uint32_t)((buf ^ 1) * 9216);
            #pragma unroll
            for (int p = 0; p < 4; p++) {
                int idx = tid + p * 128;
                int r = idx >> 3, k8 = idx & 7;
                uint32_t off = bo + (uint32_t)(r * 144 + k8 * 16);
                cp16(aB + off, A  + (size_t)(rowbase + r) * C_ + k0 + k8 * 8);
                cp16(bB + off, Wt + (size_t)(colbase + r) * C_ + k0 + k8 * 8);
            }
            CPCOMMIT();
        }
        gemm_frag_f16(aB, bB, buf, wM, wN, ofA, ofB, acc);
    }

    int h = blockIdx.x;
    int bb = rowbase >> 11, nbase = rowbase & (N_ - 1);
    if (z != 2) {
        __half* out = z ? K : Q;
        float sc = z ? 1.0f : SCALE;
        #pragma unroll
        for (int mf = 0; mf < 2; mf++) {
            int rl = wM * 32 + mf * 16 + g;
            #pragma unroll
            for (int nf = 0; nf < 4; nf++) {
                int d = wN * 32 + nf * 8 + 2 * c;
                float b0 = bias[colbase + d], b1 = bias[colbase + d + 1];
                __half2 h0 = __floats2half2_rn((acc[mf][nf][0] + b0) * sc,
                                               (acc[mf][nf][1] + b1) * sc);
                __half2 h1 = __floats2half2_rn((acc[mf][nf][2] + b0) * sc,
                                               (acc[mf][nf][3] + b1) * sc);
                *reinterpret_cast<__half2*>(
                    out + (((size_t)bb * H_ + h) * N_ + nbase + rl) * HD + d) = h0;
                *reinterpret_cast<__half2*>(
                    out + (((size_t)bb * H_ + h) * N_ + nbase + rl + 8) * HD + d) = h1;
            }
        }
    } else {
        // V: transpose through smem -> [b,h,d,n] fp16
        __syncthreads();
        float* tb = (float*)sAc;   // [64][65] floats = 16640 B <= 18432
        #pragma unroll
        for (int mf = 0; mf < 2; mf++) {
            int rl = wM * 32 + mf * 16 + g;
            #pragma unroll
            for (int nf = 0; nf < 4; nf++) {
                int d = wN * 32 + nf * 8 + 2 * c;
                float b0 = bias[colbase + d], b1 = bias[colbase + d + 1];
                tb[d * 65 + rl]           = acc[mf][nf][0] + b0;
                tb[(d + 1) * 65 + rl]     = acc[mf][nf][1] + b1;
                tb[d * 65 + rl + 8]       = acc[mf][nf][2] + b0;
                tb[(d + 1) * 65 + rl + 8] = acc[mf][nf][3] + b1;
            }
        }
        __syncthreads();
        #pragma unroll
        for (int p = 0; p < 8; p++) {
            int idx = tid + p * 128;
            int d = idx >> 4, n4 = idx & 15;
            __half2 v0 = __floats2half2_rn(tb[d * 65 + n4 * 4],     tb[d * 65 + n4 * 4 + 1]);
            __half2 v1 = __floats2half2_rn(tb[d * 65 + n4 * 4 + 2], tb[d * 65 + n4 * 4 + 3]);
            uint2 st = make_uint2(*reinterpret_cast<uint32_t*>(&v0),
                                  *reinterpret_cast<uint32_t*>(&v1));
            *reinterpret_cast<uint2*>(
                V + (((size_t)bb * H_ + h) * HD + d) * N_ + nbase + n4 * 4) = st;
        }
    }
}

// ============================================================================
// Flash attention fp16 (round-12 verified): 128 q/CTA, 4 warps x 32 q-rows.
// smem bytes: Ks 2*9216, Vs 2*9216, Ps 4*4608, ms 512  -> 55808
// ============================================================================
#define AKSB(buf) ((buf) * 9216)
#define AVSB(buf) (18432 + (buf) * 9216)
#define APSB      36864
#define AMSB      55296
#define ATTN_SMB  55808

__global__ __launch_bounds__(128, 2) void attn_t(
    const __half* __restrict__ Q, const __half* __restrict__ K,
    const __half* __restrict__ Vt, const int* __restrict__ mask,
    __half* __restrict__ O)
{
    extern __shared__ char smc[];
    float* ms = (float*)(smc + AMSB);
    uint32_t sb = (uint32_t)__cvta_generic_to_shared(smc);

    int bh = blockIdx.y, b = bh >> 3;
    int qbase = blockIdx.x * 128;
    int tid = threadIdx.x, wid = tid >> 5, lane = tid & 31;
    int g = lane >> 2, c = lane & 3;
    int r0 = qbase + wid * 32 + g;
    const size_t kvb = (size_t)bh * N_ * HD;

    int sel = lane >> 3, l8 = lane & 7;
    uint32_t ofB = (uint32_t)(((sel >> 1) * 8 + l8) * 144 + (sel & 1) * 16);
    uint32_t ofA = (uint32_t)(((sel & 1) * 8 + l8) * 144 + (sel >> 1) * 16);
    uint32_t pbase = sb + (uint32_t)(APSB + wid * 4608) + ofA;

    uint32_t qf[2][4][4];
    #pragma unroll
    for (int mf = 0; mf < 2; mf++) {
        const uint32_t* Qp = reinterpret_cast<const uint32_t*>(
            Q + ((size_t)bh * N_ + r0 + 16 * mf) * HD);
        #pragma unroll
        for (int ks = 0; ks < 4; ks++) {
            qf[mf][ks][0] = Qp[ks * 8 + c];
            qf[mf][ks][1] = Qp[256 + ks * 8 + c];
            qf[mf][ks][2] = Qp[ks * 8 + 4 + c];
            qf[mf][ks][3] = Qp[256 + ks * 8 + 4 + c];
        }
    }

    #pragma unroll
    for (int p = 0; p < 4; p++) {
        int idx = tid + p * 128;
        int key = idx >> 3, d8 = idx & 7;
        cp16(sb + (uint32_t)(AKSB(0) + key * 144 + d8 * 16),
             K + kvb + (size_t)key * HD + d8 * 8);
    }
    #pragma unroll
    for (int p = 0; p < 4; p++) {
        int idx = tid + p * 128;
        int d = idx >> 3, k8 = idx & 7;
        cp16(sb + (uint32_t)(AVSB(0) + d * 144 + k8 * 16),
             Vt + kvb + (size_t)d * N_ + k8 * 8);
    }
    CPCOMMIT();
    if (tid < 64) ms[tid] = mask[b * N_ + tid] ? 0.0f : -10000.0f;

    float of[2][8][4] = {};
    float mx[4] = {-1e30f, -1e30f, -1e30f, -1e30f};
    float lsum[4] = {};

    for (int t = 0; t < 32; t++) {
        int buf = t & 1;
        CPWAIT0();
        __syncthreads();
        int mreg = 0;
        if (t < 31) {
            int kn = (t + 1) * 64;
            #pragma unroll
            for (int p = 0; p < 4; p++) {
                int idx = tid + p * 128;
                int key = idx >> 3, d8 = idx & 7;
                cp16(sb + (uint32_t)(AKSB(buf ^ 1) + key * 144 + d8 * 16),
                     K + kvb + (size_t)(kn + key) * HD + d8 * 8);
            }
            #pragma unroll
            for (int p = 0; p < 4; p++) {
                int idx = tid + p * 128;
                int d = idx >> 3, k8 = idx & 7;
                cp16(sb + (uint32_t)(AVSB(buf ^ 1) + d * 144 + k8 * 16),
                     Vt + kvb + (size_t)d * N_ + kn + k8 * 8);
            }
            CPCOMMIT();
            if (tid < 64) mreg = mask[b * N_ + kn + tid];
        }

        uint32_t kb = sb + (uint32_t)AKSB(buf) + ofB;
        float sacc[2][8][4] = {};
        #pragma unroll
        for (int ks = 0; ks < 4; ks++) {
            #pragma unroll
            for (int p = 0; p < 4; p++) {
                uint32_t b0, b1, b2, b3;
                ldsm4(b0, b1, b2, b3, kb + (uint32_t)(p * 2304 + ks * 32));
                #pragma unroll
                for (int mf = 0; mf < 2; mf++) {
                    mma_f16(sacc[mf][2*p],   qf[mf][ks][0], qf[mf][ks][1],
                            qf[mf][ks][2], qf[mf][ks][3], b0, b1);
                    mma_f16(sacc[mf][2*p+1], qf[mf][ks][0], qf[mf][ks][1],
                            qf[mf][ks][2], qf[mf][ks][3], b2, b3);
                }
            }
        }

        const float* msp = ms + buf * 64;
        #pragma unroll
        for (int mf = 0; mf < 2; mf++) {
            float t0 = -1e30f, t1 = -1e30f;
            #pragma unroll
            for (int nf = 0; nf < 8; nf++) {
                float ma = msp[nf * 8 + 2 * c], mb = msp[nf * 8 + 2 * c + 1];
                sacc[mf][nf][0] += ma; sacc[mf][nf][1] += mb;
                sacc[mf][nf][2] += ma; sacc[mf][nf][3] += mb;
                t0 = fmaxf(t0, fmaxf(sacc[mf][nf][0], sacc[mf][nf][1]));
                t1 = fmaxf(t1, fmaxf(sacc[mf][nf][2], sacc[mf][nf][3]));
            }
            t0 = fmaxf(t0, __shfl_xor_sync(~0u, t0, 1));
            t0 = fmaxf(t0, __shfl_xor_sync(~0u, t0, 2));
            t1 = fmaxf(t1, __shfl_xor_sync(~0u, t1, 1));
            t1 = fmaxf(t1, __shfl_xor_sync(~0u, t1, 2));
            float mn0 = fmaxf(mx[mf*2],   t0);
            float mn1 = fmaxf(mx[mf*2+1], t1);
            if (mn0 > mx[mf*2] || mn1 > mx[mf*2+1]) {
                float co0 = __expf(mx[mf*2] - mn0), co1 = __expf(mx[mf*2+1] - mn1);
                lsum[mf*2] *= co0; lsum[mf*2+1] *= co1;
                #pragma unroll
                for (int nf = 0; nf < 8; nf++) {
                    of[mf][nf][0] *= co0; of[mf][nf][1] *= co0;
                    of[mf][nf][2] *= co1; of[mf][nf][3] *= co1;
                }
                mx[mf*2] = mn0; mx[mf*2+1] = mn1;
            }
        }

        #pragma unroll
        for (int mf = 0; mf < 2; mf++) {
            int rl = 16 * mf + g;
            uint32_t* pr0 = (uint32_t*)(smc + APSB + wid * 4608 + rl * 144);
            uint32_t* pr1 = (uint32_t*)(smc + APSB + wid * 4608 + (rl + 8) * 144);
            #pragma unroll
            for (int nf = 0; nf < 8; nf++) {
                float p0 = __expf(sacc[mf][nf][0] - mx[mf*2]);
                float p1 = __expf(sacc[mf][nf][1] - mx[mf*2]);
                float p2 = __expf(sacc[mf][nf][2] - mx[mf*2+1]);
                float p3 = __expf(sacc[mf][nf][3] - mx[mf*2+1]);
                lsum[mf*2]   += p0 + p1;
                lsum[mf*2+1] += p2 + p3;
                __half2 h0 = __floats2half2_rn(p0, p1);
                __half2 h1 = __floats2half2_rn(p2, p3);
                pr0[nf * 4 + c] = *reinterpret_cast<uint32_t*>(&h0);
                pr1[nf * 4 + c] = *reinterpret_cast<uint32_t*>(&h1);
            }
        }
        __syncwarp();

        uint32_t vb = sb + (uint32_t)AVSB(buf) + ofB;
        #pragma unroll
        for (int ks = 0; ks < 4; ks++) {
            uint32_t a[2][4];
            ldsm4(a[0][0], a[0][1], a[0][2], a[0][3], pbase + (uint32_t)(ks * 32));
            ldsm4(a[1][0], a[1][1], a[1][2], a[1][3],
                  pbase + (uint32_t)(16 * 144 + ks * 32));
            #pragma unroll
            for (int p = 0; p < 4; p++) {
                uint32_t b0, b1, b2, b3;
                ldsm4(b0, b1, b2, b3, vb + (uint32_t)(p * 2304 + ks * 32));
                #pragma unroll
                for (int mf = 0; mf < 2; mf++) {
                    mma_f16(of[mf][2*p],   a[mf][0], a[mf][1], a[mf][2], a[mf][3], b0, b1);
                    mma_f16(of[mf][2*p+1], a[mf][0], a[mf][1], a[mf][2], a[mf][3], b2, b3);
                }
            }
        }
        if (t < 31 && tid < 64)
            ms[(buf ^ 1) * 64 + tid] = mreg ? 0.0f : -10000.0f;
    }

    #pragma unroll
    for (int i = 0; i < 4; i++) {
        lsum[i] += __shfl_xor_sync(~0u, lsum[i], 1);
        lsum[i] += __shfl_xor_sync(~0u, lsum[i], 2);
    }
    #pragma unroll
    for (int mf = 0; mf < 2; mf++) {
        float inv0 = 1.0f / lsum[mf*2], inv1 = 1.0f / lsum[mf*2+1];
        __half* Op = O + ((size_t)bh * N_ + r0 + 16 * mf) * HD;
        #pragma unroll
        for (int nf = 0; nf < 8; nf++) {
            int d = nf * 8 + 2 * c;
            __half2 h0 = __floats2half2_rn(of[mf][nf][0] * inv0, of[mf][nf][1] * inv0);
            __half2 h1 = __floats2half2_rn(of[mf][nf][2] * inv1, of[mf][nf][3] * inv1);
            *reinterpret_cast<__half2*>(Op + d) = h0;
            *reinterpret_cast<__half2*>(Op + 8 * HD + d) = h1;
        }
    }
}

// ---------------- Output projection (fp16 operands, fp32 out) ------------------
__global__ __launch_bounds__(128) void out_gemm(
    const __half* __restrict__ AO, const float* __restrict__ bias, float* __restrict__ out)
{
    __shared__ __align__(16) char sAc[2 * 9216];
    __shared__ __align__(16) char sBc[2 * 9216];
    uint32_t aB = (uint32_t)__cvta_generic_to_shared(sAc);
    uint32_t bB = (uint32_t)__cvta_generic_to_shared(sBc);
    const __half* Wt = &g_wt[3][0];

    int tid = threadIdx.x, lane = tid & 31, wid = tid >> 5;
    int wM = wid >> 1, wN = wid & 1, g = lane >> 2, c = lane & 3;
    int rowbase = blockIdx.y * 64, colbase = blockIdx.x * 64;
    int bb = rowbase >> 11, nbase = rowbase & (N_ - 1);

    int sel = lane >> 3, l8 = lane & 7;
    uint32_t ofA = (uint32_t)(((sel & 1) * 8 + l8) * 144 + (sel >> 1) * 16);
    uint32_t ofB = (uint32_t)(((sel >> 1) * 8 + l8) * 144 + (sel & 1) * 16);

    // tile t covers k = t*64 -> head h = t
    #pragma unroll
    for (int p = 0; p < 4; p++) {
        int idx = tid + p * 128;
        int r = idx >> 3, d8 = idx & 7;
        uint32_t off = (uint32_t)(r * 144 + d8 * 16);
        cp16(aB + off, AO + (((size_t)bb * H_ + 0) * N_ + nbase + r) * HD + d8 * 8);
        cp16(bB + off, Wt + (size_t)(colbase + r) * C_ + d8 * 8);
    }
    CPCOMMIT();

    float acc[2][4][4] = {};
    for (int t = 0; t < 8; t++) {
        int buf = t & 1;
        CPWAIT0();
        __syncthreads();
        if (t < 7) {
            int h = t + 1, k0 = (t + 1) * 64;
            uint32_t bo = (uint32_t)((buf ^ 1) * 9216);
            #pragma unroll
            for (int p = 0; p < 4; p++) {
                int idx = tid + p * 128;
                int r = idx >> 3, d8 = idx & 7;
                uint32_t off = bo + (uint32_t)(r * 144 + d8 * 16);
                cp16(aB + off, AO + (((size_t)bb * H_ + h) * N_ + nbase + r) * HD + d8 * 8);
                cp16(bB + off, Wt + (size_t)(colbase + r) * C_ + k0 + d8 * 8);
            }
            CPCOMMIT();
        }
        gemm_frag_f16(aB, bB, buf, wM, wN, ofA, ofB, acc);
    }

    #pragma unroll
    for (int mf = 0; mf < 2; mf++) {
        int r = rowbase + wM * 32 + mf * 16 + g;
        #pragma unroll
        for (int nf = 0; nf < 4; nf++) {
            int cc = colbase + wN * 32 + nf * 8 + 2 * c;
            float b0 = bias[cc], b1 = bias[cc + 1];
            *reinterpret_cast<float2*>(out + (size_t)r * C_ + cc) =
                make_float2(acc[mf][nf][0] + b0, acc[mf][nf][1] + b1);
            *reinterpret_cast<float2*>(out + (size_t)(r + 8) * C_ + cc) =
                make_float2(acc[mf][nf][2] + b0, acc[mf][nf][3] + b1);
        }
    }
}

// ---------------- launch --------------------------------------------------------
extern "C" void kernel_launch(void* const* d_in, const int* in_sizes, int n_in,
                              void* d_out, int out_size)
{
    const float* x    = (const float*)d_in[0];
    const int*   mask = (const int*)  d_in[1];
    const float* ln_g = (const float*)d_in[2];
    const float* ln_b = (const float*)d_in[3];
    const float* wq   = (const float*)d_in[4];
    const float* bq   = (const float*)d_in[5];
    const float* wk   = (const float*)d_in[6];
    const float* bk   = (const float*)d_in[7];
    const float* wv   = (const float*)d_in[8];
    const float* bv   = (const float*)d_in[9];
    const float* wo   = (const float*)d_in[10];
    const float* bo   = (const float*)d_in[11];
    float* out = (float*)d_out;

    __half *xn, *q, *k, *v, *ao;
    cudaGetSymbolAddress((void**)&xn, g_xn);
    cudaGetSymbolAddress((void**)&q,  g_q);
    cudaGetSymbolAddress((void**)&k,  g_k);
    cudaGetSymbolAddress((void**)&v,  g_v);
    cudaGetSymbolAddress((void**)&ao, g_ao);

    cudaFuncSetAttribute(attn_t, cudaFuncAttributeMaxDynamicSharedMemorySize, ATTN_SMB);

    prep_w<<<dim3(16, 16, 4), 256>>>(wq, wk, wv, wo);
    ln_kernel<<<BN_, 128>>>(x, ln_g, ln_b, xn);
    qkv_gemm<<<dim3(C_ / 64, BN_ / 64, 3), 128>>>(xn, bq, bk, bv, q, k, v);
    attn_t<<<dim3(N_ / 128, BH_), 128, ATTN_SMB>>>(q, k, v, mask, ao);
    out_gemm<<<dim3(C_ / 64, BN_ / 64), 128>>>(ao, bo, out);
}